// round 9
// baseline (speedup 1.0000x reference)
#include <cuda_runtime.h>
#include <cuda_bf16.h>
#include <math.h>

#define HW2 2304
#define HH 48
#define WW 48

typedef unsigned int u32;
typedef unsigned short u16;

// ---------------- device scratch (no allocations allowed; [2] = per-branch) ----------------
__device__ float g_xenc  [2*64 *HW2];
__device__ float g_yenc  [2*64 *HW2];
__device__ float g_f512a [2][2*512*HW2];
__device__ float g_f512b [2][2*512*HW2];
__device__ float g_cols  [2][2*1600*HW2];
__device__ u16   g_colsh [2][2*4608*HW2];
__device__ u16   g_colsl [2][2*4608*HW2];
__device__ u16   g_awh   [2][2*256*2304];
__device__ u16   g_awl   [2][2*256*2304];
__device__ u16   g_dwh   [3*512*4608];
__device__ u16   g_dwl   [3*512*4608];
__device__ u16   g_s1h   [128*2304];
__device__ u16   g_s1l   [128*2304];
__device__ float g_offb  [2][2*18 *HW2];
__device__ float g_cpart [2][16*2*18*HW2];
__device__ float g_f177  [2][2*177*HW2];
__device__ float g_f177b [2][2*177*HW2];
__device__ float g_wb1   [2][2*64*576];
__device__ float g_wb2   [2][2*64*144];
__device__ float g_wb3   [2][2*256*36];
__device__ float g_fwb   [2][2*256];
__device__ float g_adw   [2][2*256*HW2];
__device__ float g_def0  [2*256*HW2];
__device__ float g_def1  [2*256*HW2];
__device__ float g_s1o   [2][2*128*HW2];
__device__ float g_s2o   [2][2*64*HW2];
__device__ float g_swa   [2*HW2];
__device__ float g_swb   [2*HW2];

// ---------------- helpers ----------------
__device__ __forceinline__ void split16(float x, u16& h, u16& l)
{
    __nv_bfloat16 xh = __float2bfloat16(x);
    h = __bfloat16_as_ushort(xh);
    l = __bfloat16_as_ushort(__float2bfloat16(x - __bfloat162float(xh)));
}

__global__ void convw_k(const float* __restrict__ src, u16* __restrict__ h,
                        u16* __restrict__ l, int n)
{
    int i = blockIdx.x * 256 + threadIdx.x;
    if (i >= n) return;
    u16 hh, ll;
    split16(src[i], hh, ll);
    h[i] = hh; l[i] = ll;
}

#define MMA16816(c, a, b0v, b1v) \
    asm volatile("mma.sync.aligned.m16n8k16.row.col.f32.bf16.bf16.f32 " \
        "{%0,%1,%2,%3},{%4,%5,%6,%7},{%8,%9},{%0,%1,%2,%3};" \
        : "+f"((c)[0]), "+f"((c)[1]), "+f"((c)[2]), "+f"((c)[3]) \
        : "r"((a)[0]), "r"((a)[1]), "r"((a)[2]), "r"((a)[3]), \
          "r"(b0v), "r"(b1v))

// ---------------- bf16x3 split tensor-core GEMM, pre-split inputs ----------------
// Term-major MMA issue: 8 independent accumulators between reuses -> hides HMMA latency.
// Per-accumulator term order unchanged (hh, hl, lh) -> bitwise identical results.
__global__ __launch_bounds__(256)
void gemm_bf3b(const u16* __restrict__ Ah, const u16* __restrict__ Al,
               const u16* __restrict__ Bh, const u16* __restrict__ Bl,
               float* __restrict__ C, int M, int N, int K,
               long long sA, long long sB, long long sC, int relu)
{
    Ah += (long long)blockIdx.z * sA;
    Al += (long long)blockIdx.z * sA;
    Bh += (long long)blockIdx.z * sB;
    Bl += (long long)blockIdx.z * sB;
    C  += (long long)blockIdx.z * sC;

    __shared__ u32 sAh[2][128][13];
    __shared__ u32 sAl[2][128][13];
    __shared__ u32 sBh[2][64][13];
    __shared__ u32 sBl[2][64][13];

    const int tid = threadIdx.x;
    const int lane = tid & 31, warp = tid >> 5;
    const int wm = warp >> 1, wn = warp & 1;
    const int m0 = blockIdx.y * 128, n0 = blockIdx.x * 64;

    const int arow = tid >> 1, ahalf = tid & 1;
    const u16* ApH = Ah + (long long)(m0 + arow) * K + ahalf * 8;
    const u16* ApL = Al + (long long)(m0 + arow) * K + ahalf * 8;

    const int bw = warp;
    const int bn = lane * 2;
    const u16* BpH = Bh + n0 + bn;
    const u16* BpL = Bl + n0 + bn;

    float acc[2][4][4];
#pragma unroll
    for (int mt = 0; mt < 2; mt++)
#pragma unroll
        for (int nt = 0; nt < 4; nt++)
#pragma unroll
            for (int i = 0; i < 4; i++) acc[mt][nt][i] = 0.f;

    uint4 lah, lal;
    u32 lbh0, lbh1, lbl0, lbl1;

    lah = *(const uint4*)ApH;
    lal = *(const uint4*)ApL;
    lbh0 = *(const u32*)(BpH + (long long)(2 * bw) * N);
    lbh1 = *(const u32*)(BpH + (long long)(2 * bw + 1) * N);
    lbl0 = *(const u32*)(BpL + (long long)(2 * bw) * N);
    lbl1 = *(const u32*)(BpL + (long long)(2 * bw + 1) * N);
    {
        sAh[0][arow][ahalf*4+0] = lah.x; sAh[0][arow][ahalf*4+1] = lah.y;
        sAh[0][arow][ahalf*4+2] = lah.z; sAh[0][arow][ahalf*4+3] = lah.w;
        sAl[0][arow][ahalf*4+0] = lal.x; sAl[0][arow][ahalf*4+1] = lal.y;
        sAl[0][arow][ahalf*4+2] = lal.z; sAl[0][arow][ahalf*4+3] = lal.w;
        sBh[0][bn  ][bw] = __byte_perm(lbh0, lbh1, 0x5410);
        sBh[0][bn+1][bw] = __byte_perm(lbh0, lbh1, 0x7632);
        sBl[0][bn  ][bw] = __byte_perm(lbl0, lbl1, 0x5410);
        sBl[0][bn+1][bw] = __byte_perm(lbl0, lbl1, 0x7632);
    }
    __syncthreads();

    const int ar = lane >> 2, ac = lane & 3;
    int buf = 0;
    for (int k0 = 0; k0 < K; k0 += 16) {
        const bool has = (k0 + 16) < K;
        if (has) {
            lah = *(const uint4*)(ApH + k0 + 16);
            lal = *(const uint4*)(ApL + k0 + 16);
            const long long r0 = (long long)(k0 + 16 + 2 * bw) * N;
            lbh0 = *(const u32*)(BpH + r0);
            lbh1 = *(const u32*)(BpH + r0 + N);
            lbl0 = *(const u32*)(BpL + r0);
            lbl1 = *(const u32*)(BpL + r0 + N);
        }

        // all fragments into registers
        u32 ah[2][4], al[2][4];
#pragma unroll
        for (int mt = 0; mt < 2; mt++) {
            int r = wm * 32 + mt * 16 + ar;
            ah[mt][0] = sAh[buf][r][ac];         al[mt][0] = sAl[buf][r][ac];
            ah[mt][1] = sAh[buf][r + 8][ac];     al[mt][1] = sAl[buf][r + 8][ac];
            ah[mt][2] = sAh[buf][r][ac + 4];     al[mt][2] = sAl[buf][r][ac + 4];
            ah[mt][3] = sAh[buf][r + 8][ac + 4]; al[mt][3] = sAl[buf][r + 8][ac + 4];
        }
        u32 bh0[4], bh1[4], bl0[4], bl1[4];
#pragma unroll
        for (int nt = 0; nt < 4; nt++) {
            int nr = wn * 32 + nt * 8 + ar;
            bh0[nt] = sBh[buf][nr][ac]; bh1[nt] = sBh[buf][nr][ac + 4];
            bl0[nt] = sBl[buf][nr][ac]; bl1[nt] = sBl[buf][nr][ac + 4];
        }

        // term-major: 8 independent MMAs per pass; per-acc order stays hh -> hl -> lh
#pragma unroll
        for (int nt = 0; nt < 4; nt++)
#pragma unroll
            for (int mt = 0; mt < 2; mt++)
                MMA16816(acc[mt][nt], ah[mt], bh0[nt], bh1[nt]);   // hi*hi
#pragma unroll
        for (int nt = 0; nt < 4; nt++)
#pragma unroll
            for (int mt = 0; mt < 2; mt++)
                MMA16816(acc[mt][nt], ah[mt], bl0[nt], bl1[nt]);   // hi*lo
#pragma unroll
        for (int nt = 0; nt < 4; nt++)
#pragma unroll
            for (int mt = 0; mt < 2; mt++)
                MMA16816(acc[mt][nt], al[mt], bh0[nt], bh1[nt]);   // lo*hi

        if (has) {
            int nb = buf ^ 1;
            sAh[nb][arow][ahalf*4+0] = lah.x; sAh[nb][arow][ahalf*4+1] = lah.y;
            sAh[nb][arow][ahalf*4+2] = lah.z; sAh[nb][arow][ahalf*4+3] = lah.w;
            sAl[nb][arow][ahalf*4+0] = lal.x; sAl[nb][arow][ahalf*4+1] = lal.y;
            sAl[nb][arow][ahalf*4+2] = lal.z; sAl[nb][arow][ahalf*4+3] = lal.w;
            sBh[nb][bn  ][bw] = __byte_perm(lbh0, lbh1, 0x5410);
            sBh[nb][bn+1][bw] = __byte_perm(lbh0, lbh1, 0x7632);
            sBl[nb][bn  ][bw] = __byte_perm(lbl0, lbl1, 0x5410);
            sBl[nb][bn+1][bw] = __byte_perm(lbl0, lbl1, 0x7632);
        }
        __syncthreads();
        buf ^= 1;
    }

#pragma unroll
    for (int mt = 0; mt < 2; mt++) {
        int r = m0 + wm * 32 + mt * 16 + ar;
#pragma unroll
        for (int nt = 0; nt < 4; nt++) {
            int c = n0 + wn * 32 + nt * 8 + ac * 2;
            float2 v0 = make_float2(acc[mt][nt][0], acc[mt][nt][1]);
            float2 v1 = make_float2(acc[mt][nt][2], acc[mt][nt][3]);
            if (relu) {
                v0.x = fmaxf(v0.x, 0.f); v0.y = fmaxf(v0.y, 0.f);
                v1.x = fmaxf(v1.x, 0.f); v1.y = fmaxf(v1.y, 0.f);
            }
            *(float2*)&C[(long long)r * N + c] = v0;
            *(float2*)&C[(long long)(r + 8) * N + c] = v1;
        }
    }
}

// ---------------- aligned fast fp32 GEMM ----------------
template<int RN>
__global__ __launch_bounds__(256)
void gemm_al(const float* __restrict__ A, const float* __restrict__ B,
             float* __restrict__ C, int M, int N, int K,
             long long sA, long long sB, long long sC,
             const float* __restrict__ bias, int relu)
{
    constexpr int TN = 16 * RN;
    A += (long long)blockIdx.z * sA;
    B += (long long)blockIdx.z * sB;
    C += (long long)blockIdx.z * sC;

    __shared__ float As[2][16][68];
    __shared__ float Bs[2][16][TN];

    const int tid = threadIdx.x;
    const int tx = tid & 15, ty = tid >> 4;
    const int m0 = blockIdx.y * 64, n0 = blockIdx.x * TN;

    const int ar = tid >> 2;
    const int ak = (tid & 3) * 4;
    const int bk = tid >> 4;
    const int bn = (tid & 15) * RN;

    const float* Ap = A + (long long)(m0 + ar) * K + ak;
    const float* Bp = B + (long long)bk * N + n0 + bn;

    float acc[4][RN];
#pragma unroll
    for (int i = 0; i < 4; i++)
#pragma unroll
        for (int j = 0; j < RN; j++) acc[i][j] = 0.f;

    {
        float4 av = *(const float4*)Ap;
        As[0][ak + 0][ar] = av.x; As[0][ak + 1][ar] = av.y;
        As[0][ak + 2][ar] = av.z; As[0][ak + 3][ar] = av.w;
#pragma unroll
        for (int h = 0; h < RN / 4; h++)
            *(float4*)&Bs[0][bk][bn + h * 4] = *(const float4*)(Bp + h * 4);
    }
    __syncthreads();

    int buf = 0;
    for (int k0 = 0; k0 < K; k0 += 16) {
        const bool has = (k0 + 16) < K;
        float4 la;
        float4 lbv[RN / 4];
        if (has) {
            la = *(const float4*)(Ap + k0 + 16);
#pragma unroll
            for (int h = 0; h < RN / 4; h++)
                lbv[h] = *(const float4*)(Bp + (long long)(k0 + 16) * N + h * 4);
        }

#pragma unroll
        for (int kk = 0; kk < 16; kk++) {
            float4 a4 = *(const float4*)&As[buf][kk][ty * 4];
            float a[4] = {a4.x, a4.y, a4.z, a4.w};
            float b[RN];
#pragma unroll
            for (int h = 0; h < RN / 4; h++) {
                float4 b4 = *(const float4*)&Bs[buf][kk][h * 64 + tx * 4];
                b[h * 4 + 0] = b4.x; b[h * 4 + 1] = b4.y;
                b[h * 4 + 2] = b4.z; b[h * 4 + 3] = b4.w;
            }
#pragma unroll
            for (int i = 0; i < 4; i++)
#pragma unroll
                for (int j = 0; j < RN; j++) acc[i][j] += a[i] * b[j];
        }

        if (has) {
            int nb = buf ^ 1;
            As[nb][ak + 0][ar] = la.x; As[nb][ak + 1][ar] = la.y;
            As[nb][ak + 2][ar] = la.z; As[nb][ak + 3][ar] = la.w;
#pragma unroll
            for (int h = 0; h < RN / 4; h++)
                *(float4*)&Bs[nb][bk][bn + h * 4] = lbv[h];
        }
        __syncthreads();
        buf ^= 1;
    }

#pragma unroll
    for (int i = 0; i < 4; i++) {
        int m = m0 + ty * 4 + i;
        float bv = bias ? bias[m] : 0.f;
#pragma unroll
        for (int h = 0; h < RN / 4; h++) {
            float4 v;
            v.x = acc[i][h * 4 + 0] + bv;
            v.y = acc[i][h * 4 + 1] + bv;
            v.z = acc[i][h * 4 + 2] + bv;
            v.w = acc[i][h * 4 + 3] + bv;
            if (relu) {
                v.x = fmaxf(v.x, 0.f); v.y = fmaxf(v.y, 0.f);
                v.z = fmaxf(v.z, 0.f); v.w = fmaxf(v.w, 0.f);
            }
            *(float4*)&C[(long long)m * N + n0 + h * 64 + tx * 4] = v;
        }
    }
}

// ---------------- fallback 64x64 GEMM (any shape) ----------------
__global__ void gemm64(const float* __restrict__ A, const float* __restrict__ B,
                       float* __restrict__ C, int M, int N, int K,
                       long long sA, long long sB, long long sC,
                       const float* __restrict__ bias, int relu)
{
    A += (long long)blockIdx.z * sA;
    B += (long long)blockIdx.z * sB;
    C += (long long)blockIdx.z * sC;
    __shared__ float As[16][64];
    __shared__ float Bs[16][68];
    int tx = threadIdx.x, ty = threadIdx.y;
    int tid = ty * 16 + tx;
    int m0 = blockIdx.y * 64, n0 = blockIdx.x * 64;
    int mA = tid >> 2, kA = (tid & 3) * 4;
    int kB = tid >> 4, nB = (tid & 15) * 4;
    float acc[4][4];
#pragma unroll
    for (int i = 0; i < 4; i++)
#pragma unroll
        for (int j = 0; j < 4; j++) acc[i][j] = 0.f;

    for (int k0 = 0; k0 < K; k0 += 16) {
#pragma unroll
        for (int i = 0; i < 4; i++) {
            int k = k0 + kA + i;
            As[kA + i][mA] = (m0 + mA < M && k < K) ? A[(long long)(m0 + mA) * K + k] : 0.f;
        }
#pragma unroll
        for (int i = 0; i < 4; i++) {
            int n = n0 + nB + i;
            Bs[kB][nB + i] = (k0 + kB < K && n < N) ? B[(long long)(k0 + kB) * N + n] : 0.f;
        }
        __syncthreads();
#pragma unroll
        for (int kk = 0; kk < 16; kk++) {
            float a[4], b[4];
#pragma unroll
            for (int i = 0; i < 4; i++) a[i] = As[kk][ty * 4 + i];
#pragma unroll
            for (int j = 0; j < 4; j++) b[j] = Bs[kk][tx * 4 + j];
#pragma unroll
            for (int i = 0; i < 4; i++)
#pragma unroll
                for (int j = 0; j < 4; j++) acc[i][j] += a[i] * b[j];
        }
        __syncthreads();
    }
#pragma unroll
    for (int i = 0; i < 4; i++) {
        int m = m0 + ty * 4 + i;
        if (m >= M) continue;
        float bv = bias ? bias[m] : 0.f;
#pragma unroll
        for (int j = 0; j < 4; j++) {
            int n = n0 + tx * 4 + j;
            if (n >= N) continue;
            float v = acc[i][j] + bv;
            if (relu) v = fmaxf(v, 0.f);
            C[(long long)m * N + n] = v;
        }
    }
}

// ---------------- 512->18 offset-head 3x3 conv ----------------
__global__ void conv18_k(const float* __restrict__ in, long long inB,
                         const float* __restrict__ w, float* __restrict__ part, int C)
{
    const int t = blockIdx.x, cc = blockIdx.y, b = blockIdx.z;
    const int tid = threadIdx.x;
    const int hw = t * 256 + tid;
    const int h = hw / WW, x = hw % WW;
    const int hf = (t * 256) / WW;

    __shared__ float sIn[4][9 * WW];
    __shared__ float sW[4][18 * 9];

    float acc[18];
#pragma unroll
    for (int o = 0; o < 18; o++) acc[o] = 0.f;

    const float* ib = in + (long long)b * inB + (long long)(cc * 32) * HW2;
    const int lr = h - (hf - 1);

    for (int cs = 0; cs < 32; cs += 4) {
        for (int i = tid; i < 4 * 9 * WW; i += 256) {
            int c = i / (9 * WW), r = i % (9 * WW);
            int row = hf - 1 + r / WW, col = r % WW;
            float v = 0.f;
            if (row >= 0 && row < HH) v = ib[(long long)(cs + c) * HW2 + row * WW + col];
            sIn[c][r] = v;
        }
        for (int i = tid; i < 4 * 162; i += 256) {
            int c = i / 162, r = i % 162;
            int o = r / 9, q = r % 9;
            sW[c][r] = w[((long long)o * C + (cc * 32 + cs + c)) * 9 + q];
        }
        __syncthreads();

#pragma unroll
        for (int c = 0; c < 4; c++) {
            float tap[9];
#pragma unroll
            for (int ki = 0; ki < 3; ki++)
#pragma unroll
                for (int kj = 0; kj < 3; kj++) {
                    int xx = x - 1 + kj;
                    float v = 0.f;
                    if (xx >= 0 && xx < WW) v = sIn[c][(lr - 1 + ki) * WW + xx];
                    tap[ki * 3 + kj] = v;
                }
#pragma unroll
            for (int o = 0; o < 18; o++) {
                float s = acc[o];
#pragma unroll
                for (int q = 0; q < 9; q++) s += sW[c][o * 9 + q] * tap[q];
                acc[o] = s;
            }
        }
        __syncthreads();
    }

    float* pp = part + ((long long)cc * 2 + b) * 18 * HW2;
#pragma unroll
    for (int o = 0; o < 18; o++) pp[(long long)o * HW2 + hw] = acc[o];
}

__global__ void reduce18_k(const float* __restrict__ part, float* __restrict__ out)
{
    int idx = blockIdx.x * 256 + threadIdx.x;
    if (idx >= 2 * 18 * HW2) return;
    int b = idx / (18 * HW2);
    int r = idx % (18 * HW2);
    float s = 0.f;
#pragma unroll
    for (int c = 0; c < 16; c++) s += part[((long long)c * 2 + b) * 18 * HW2 + r];
    out[(long long)b * 18 * HW2 + r] = s;
}

// ---------------- deformable (or plain) 3x3 s1 p1 im2col ----------------
__global__ void deform_im2col_k(const float* __restrict__ src, long long srcB,
                                const float* __restrict__ off,
                                float* __restrict__ colsF,
                                u16* __restrict__ colsH, u16* __restrict__ colsL,
                                int C, int mode)
{
    int hw = blockIdx.x * 256 + threadIdx.x;
    if (hw >= HW2) return;
    int bq = blockIdx.y;
    int b = bq / 9, q = bq % 9;
    int ki = q / 3, kj = q % 3;
    int h = hw / WW, w = hw % WW;
    const float* sb = src + (long long)b * srcB;
    long long cbase = (long long)b * C * 9 * HW2;
    int c0 = blockIdx.z * 64;
    int c1 = c0 + 64; if (c1 > C) c1 = C;

    float w00, w01, w10, w11;
    int i00, i01, i10, i11;
    if (off == nullptr) {
        int y = h - 1 + ki, x = w - 1 + kj;
        bool vin = (y >= 0 && y < HH && x >= 0 && x < WW);
        w00 = vin ? 1.f : 0.f; w01 = w10 = w11 = 0.f;
        i00 = vin ? (y * WW + x) : 0; i01 = i10 = i11 = 0;
    } else {
        float py = (float)(h - 1 + ki) + off[((long long)b * 18 + 2 * q) * HW2 + hw];
        float px = (float)(w - 1 + kj) + off[((long long)b * 18 + 2 * q + 1) * HW2 + hw];
        float fy = floorf(py), fx = floorf(px);
        float ay = py - fy, ax = px - fx;
        int y0 = (int)fy, x0 = (int)fx;
        int y1 = y0 + 1, x1 = x0 + 1;
        bool by0 = (y0 >= 0 && y0 < HH), by1 = (y1 >= 0 && y1 < HH);
        bool bx0 = (x0 >= 0 && x0 < WW), bx1 = (x1 >= 0 && x1 < WW);
        int yc0 = min(max(y0, 0), HH - 1), yc1 = min(max(y1, 0), HH - 1);
        int xc0 = min(max(x0, 0), WW - 1), xc1 = min(max(x1, 0), WW - 1);
        w00 = (by0 && bx0) ? (1.f - ay) * (1.f - ax) : 0.f;
        w01 = (by0 && bx1) ? (1.f - ay) * ax : 0.f;
        w10 = (by1 && bx0) ? ay * (1.f - ax) : 0.f;
        w11 = (by1 && bx1) ? ay * ax : 0.f;
        i00 = yc0 * WW + xc0; i01 = yc0 * WW + xc1;
        i10 = yc1 * WW + xc0; i11 = yc1 * WW + xc1;
    }

    for (int c = c0; c < c1; c++) {
        const float* s = sb + (long long)c * HW2;
        float v = w00 * s[i00] + w01 * s[i01] + w10 * s[i10] + w11 * s[i11];
        long long idx = cbase + ((long long)c * 9 + q) * HW2 + hw;
        if (mode == 0) {
            colsF[idx] = v;
        } else {
            u16 hh, ll;
            split16(v, hh, ll);
            colsH[idx] = hh; colsL[idx] = ll;
        }
    }
}

// ---------------- generic strided im2col ----------------
__global__ void im2col_g(const float* __restrict__ src, long long srcB,
                         float* __restrict__ cols,
                         int C, int H, int W, int KH, int KW,
                         int stride, int pad, int OH, int OW)
{
    int ohw = blockIdx.x * 256 + threadIdx.x;
    int OHW = OH * OW;
    if (ohw >= OHW) return;
    int row = blockIdx.y;
    int b = blockIdx.z;
    int kk = row % (KH * KW);
    int c = row / (KH * KW);
    int kh = kk / KW, kw = kk % KW;
    int oh = ohw / OW, ow = ohw % OW;
    int ih = oh * stride - pad + kh;
    int iw = ow * stride - pad + kw;
    float v = 0.f;
    if (ih >= 0 && ih < H && iw >= 0 && iw < W)
        v = src[(long long)b * srcB + ((long long)c * H + ih) * W + iw];
    cols[((long long)b * C * KH * KW + row) * OHW + ohw] = v;
}

// ---------------- direct 3x3 conv (tiny s3: 64->1) ----------------
__global__ void conv3x3_direct(const float* __restrict__ in, long long inB,
                               const float* __restrict__ w, float* __restrict__ out,
                               long long outB, int C, int relu)
{
    int hw = blockIdx.x * 256 + threadIdx.x;
    if (hw >= HW2) return;
    int o = blockIdx.y, b = blockIdx.z;
    int h = hw / WW, x = hw % WW;
    const float* ib = in + (long long)b * inB;
    const float* wo = w + (long long)o * C * 9;
    float acc = 0.f;
    for (int c = 0; c < C; c++) {
        const float* ic = ib + (long long)c * HW2;
        const float* wc = wo + c * 9;
#pragma unroll
        for (int kh = 0; kh < 3; kh++) {
            int ih = h + kh - 1;
            if (ih < 0 || ih >= HH) continue;
#pragma unroll
            for (int kw = 0; kw < 3; kw++) {
                int iw = x + kw - 1;
                if (iw < 0 || iw >= WW) continue;
                acc += ic[ih * WW + iw] * wc[kh * 3 + kw];
            }
        }
    }
    if (relu) acc = fmaxf(acc, 0.f);
    out[(long long)b * outB + (long long)o * HW2 + hw] = acc;
}

// ---------------- elementwise kernels ----------------
__global__ void concat_k(const float* __restrict__ a, const float* __restrict__ b_,
                         float* __restrict__ o, long long imgStride)
{
    int idx = blockIdx.x * 256 + threadIdx.x;
    if (idx >= 2 * 512 * HW2) return;
    int bb = idx / (512 * HW2);
    int c = (idx / HW2) % 512;
    int hw = idx % HW2;
    float v = (c < 256) ? a[bb * imgStride + (long long)c * HW2 + hw]
                        : b_[bb * imgStride + (long long)(c - 256) * HW2 + hw];
    o[idx] = v;
}

__global__ void corr_k(const float* __restrict__ Ra, const float* __restrict__ Tb,
                       float* __restrict__ f177)
{
    int idx = blockIdx.x * 256 + threadIdx.x;
    if (idx >= 2 * 49 * HW2) return;
    int b = idx / (49 * HW2);
    int q = (idx / HW2) % 49;
    int hw = idx % HW2;
    int h = hw / WW, w = hw % WW;
    int dy = 2 * ((q / 7) - 3), dx = 2 * ((q % 7) - 3);
    int hh = h + dy, ww = w + dx;
    float s = 0.f;
    if (hh >= 0 && hh < HH && ww >= 0 && ww < WW) {
        const float* a = Ra + (long long)b * (2 * 64 * HW2) + hw;
        const float* bp = Tb + (long long)b * (2 * 64 * HW2) + hh * WW + ww;
        for (int c = 0; c < 64; c++) s += a[c * HW2] * bp[c * HW2];
    }
    f177[((long long)b * 177 + q) * HW2 + hw] = s * (1.f / 64.f);
}

__global__ void pack_k(const float* __restrict__ eA, const float* __restrict__ eB,
                       float* __restrict__ f177)
{
    int idx = blockIdx.x * 256 + threadIdx.x;
    if (idx >= 2 * 64 * HW2) return;
    int b = idx / (64 * HW2);
    int c = (idx / HW2) % 64;
    int hw = idx % HW2;
    f177[((long long)b * 177 + 49 + c) * HW2 + hw] = eA[idx];
    f177[((long long)b * 177 + 113 + c) * HW2 + hw] = eB[idx];
}

__global__ void mean36_k(const float* __restrict__ in, float* __restrict__ fw, int total)
{
    int i = blockIdx.x * 256 + threadIdx.x;
    if (i >= total) return;
    float s = 0.f;
#pragma unroll
    for (int j = 0; j < 36; j++) s += in[i * 36 + j];
    fw[i] = s * (1.f / 36.f);
}

__global__ void mkw_k(const float* __restrict__ fw, const float* __restrict__ Wt,
                      const float* __restrict__ Bi, float* __restrict__ adw,
                      int M, int Kc, int total)
{
    int idx = blockIdx.x * 256 + threadIdx.x;
    if (idx >= total) return;
    int b = idx / (M * Kc);
    int r = idx - b * M * Kc;
    int o = r / Kc;
    adw[idx] = fw[b * M + o] * Wt[r] + Bi[r];
}

__global__ void final_k(const float* __restrict__ d0, const float* __restrict__ d1,
                        const float* __restrict__ s0p, const float* __restrict__ s1p,
                        float* __restrict__ out, int total)
{
    int idx = blockIdx.x * 256 + threadIdx.x;
    if (idx >= total) return;
    int b = idx / (256 * HW2);
    int hw = idx % HW2;
    float s0 = s0p[b * HW2 + hw];
    float s1 = s1p[b * HW2 + hw];
    const float eps = 1e-8f;
    float wx = (s0 * s1) / (fmaxf(fabsf(s0), eps) * fmaxf(fabsf(s1), eps));
    float wy = (s1 * s1) / (fmaxf(fabsf(s1), eps) * fmaxf(fabsf(s1), eps));
    float mx = fmaxf(wx, wy);
    float e0 = expf(wx - mx), e1 = expf(wy - mx);
    float inv = 1.f / (e0 + e1);
    out[idx] = d0[idx] * (e0 * inv) + d1[idx] * (e1 * inv);
}

// ---------------- host orchestration (4-lane stream overlap) ----------------
extern "C" void kernel_launch(void* const* d_in, const int* in_sizes, int n_in,
                              void* d_out, int out_size)
{
    (void)in_sizes; (void)n_in; (void)out_size;
    const float* R0     = (const float*)d_in[0];
    const float* T0     = (const float*)d_in[1];
    const float* inp    = (const float*)d_in[2];
    const float* enc0_w = (const float*)d_in[3];
    const float* enc0_b = (const float*)d_in[4];
    const float* enc1_w = (const float*)d_in[5];
    const float* enc1_b = (const float*)d_in[6];
    const float* offw[4] = {(const float*)d_in[7], (const float*)d_in[8],
                            (const float*)d_in[9], (const float*)d_in[10]};
    const float* defw[3] = {(const float*)d_in[11], (const float*)d_in[12],
                            (const float*)d_in[13]};
    const float* w0a = (const float*)d_in[14];
    const float* w0b = (const float*)d_in[15];
    const float* w0c = (const float*)d_in[16];
    const float* w1a = (const float*)d_in[17];
    const float* w1b = (const float*)d_in[18];
    const float* w1c = (const float*)d_in[19];
    const float* wx_w  = (const float*)d_in[20];
    const float* wx_b  = (const float*)d_in[21];
    const float* wxf_w = (const float*)d_in[22];
    const float* wxf_b = (const float*)d_in[23];
    const float* s1w = (const float*)d_in[24];
    const float* s2w = (const float*)d_in[25];
    const float* s3w = (const float*)d_in[26];
    float* out = (float*)d_out;

    float *xenc, *yenc, *def0, *def1, *swa, *swb;
    float *f512aP, *f512bP, *colsP, *offP, *cpartP, *f177P, *f177bP;
    float *wb1P, *wb2P, *wb3P, *fwP, *adwP, *s1oP, *s2oP;
    u16 *colshP, *colslP, *awhP, *awlP, *dwh, *dwl, *s1h, *s1l;
    cudaGetSymbolAddress((void**)&xenc,   g_xenc);
    cudaGetSymbolAddress((void**)&yenc,   g_yenc);
    cudaGetSymbolAddress((void**)&f512aP, g_f512a);
    cudaGetSymbolAddress((void**)&f512bP, g_f512b);
    cudaGetSymbolAddress((void**)&colsP,  g_cols);
    cudaGetSymbolAddress((void**)&colshP, g_colsh);
    cudaGetSymbolAddress((void**)&colslP, g_colsl);
    cudaGetSymbolAddress((void**)&awhP,   g_awh);
    cudaGetSymbolAddress((void**)&awlP,   g_awl);
    cudaGetSymbolAddress((void**)&dwh,    g_dwh);
    cudaGetSymbolAddress((void**)&dwl,    g_dwl);
    cudaGetSymbolAddress((void**)&s1h,    g_s1h);
    cudaGetSymbolAddress((void**)&s1l,    g_s1l);
    cudaGetSymbolAddress((void**)&offP,   g_offb);
    cudaGetSymbolAddress((void**)&cpartP, g_cpart);
    cudaGetSymbolAddress((void**)&f177P,  g_f177);
    cudaGetSymbolAddress((void**)&f177bP, g_f177b);
    cudaGetSymbolAddress((void**)&wb1P,   g_wb1);
    cudaGetSymbolAddress((void**)&wb2P,   g_wb2);
    cudaGetSymbolAddress((void**)&wb3P,   g_wb3);
    cudaGetSymbolAddress((void**)&fwP,    g_fwb);
    cudaGetSymbolAddress((void**)&adwP,   g_adw);
    cudaGetSymbolAddress((void**)&def0,   g_def0);
    cudaGetSymbolAddress((void**)&def1,   g_def1);
    cudaGetSymbolAddress((void**)&s1oP,   g_s1o);
    cudaGetSymbolAddress((void**)&s2oP,   g_s2o);
    cudaGetSymbolAddress((void**)&swa,    g_swa);
    cudaGetSymbolAddress((void**)&swb,    g_swb);

    auto F512A = [&](int br){ return f512aP + (long long)br * (2*512*HW2); };
    auto F512B = [&](int br){ return f512bP + (long long)br * (2*512*HW2); };
    auto COLS  = [&](int br){ return colsP  + (long long)br * (2*1600*HW2); };
    auto COLSH = [&](int br){ return colshP + (long long)br * (2LL*4608*HW2); };
    auto COLSL = [&](int br){ return colslP + (long long)br * (2LL*4608*HW2); };
    auto AWH   = [&](int br){ return awhP   + (long long)br * (2*256*2304); };
    auto AWL   = [&](int br){ return awlP   + (long long)br * (2*256*2304); };
    auto OFF   = [&](int br){ return offP   + (long long)br * (2*18*HW2); };
    auto CPART = [&](int br){ return cpartP + (long long)br * (16LL*2*18*HW2); };
    auto F177  = [&](int br){ return f177P  + (long long)br * (2*177*HW2); };
    auto F177B = [&](int br){ return f177bP + (long long)br * (2*177*HW2); };
    auto WB1   = [&](int br){ return wb1P + (long long)br * (2*64*576); };
    auto WB2   = [&](int br){ return wb2P + (long long)br * (2*64*144); };
    auto WB3   = [&](int br){ return wb3P + (long long)br * (2*256*36); };
    auto FW    = [&](int br){ return fwP  + (long long)br * (2*256); };
    auto ADW   = [&](int br){ return adwP + (long long)br * (2*256*HW2); };
    auto S1O   = [&](int br){ return s1oP + (long long)br * (2*128*HW2); };
    auto S2O   = [&](int br){ return s2oP + (long long)br * (2*64*HW2); };

    const long long imgStride = 2LL * 256 * HW2;
    const int DW = 512 * 4608;

    cudaStream_t sM = 0, sW0, sS1, sW1;
    cudaStreamCreateWithFlags(&sW0, cudaStreamNonBlocking);
    cudaStreamCreateWithFlags(&sS1, cudaStreamNonBlocking);
    cudaStreamCreateWithFlags(&sW1, cudaStreamNonBlocking);
    cudaEvent_t eInit, eW0, eW1, eB1;
    cudaEventCreateWithFlags(&eInit, cudaEventDisableTiming);
    cudaEventCreateWithFlags(&eW0,   cudaEventDisableTiming);
    cudaEventCreateWithFlags(&eW1,   cudaEventDisableTiming);
    cudaEventCreateWithFlags(&eB1,   cudaEventDisableTiming);

    auto GEMMTB = [&](cudaStream_t st, const u16* Ah, const u16* Al,
                      const u16* Bh, const u16* Bl, float* C,
                      int M, int N, int K,
                      long long sA, long long sB, long long sC, int relu) {
        gemm_bf3b<<<dim3(N / 64, M / 128, 2), 256, 0, st>>>(Ah, Al, Bh, Bl,
                                                            C, M, N, K, sA, sB, sC, relu);
    };
    auto GEMMA = [&](cudaStream_t st, const float* A, const float* Bm, float* C,
                     int M, int N, int K, long long sA, long long sB, long long sC,
                     const float* bias, int relu) {
        gemm_al<4><<<dim3(N / 64, M / 64, 2), 256, 0, st>>>(A, Bm, C, M, N, K,
                                                            sA, sB, sC, bias, relu);
    };
    auto GEMMF = [&](cudaStream_t st, const float* A, const float* Bm, float* C,
                     int M, int N, int K, long long sA, long long sB, long long sC,
                     const float* bias, int relu) {
        dim3 g((N + 63) / 64, (M + 63) / 64, 2);
        gemm64<<<g, dim3(16, 16), 0, st>>>(A, Bm, C, M, N, K, sA, sB, sC, bias, relu);
    };
    auto DIM2COL = [&](cudaStream_t st, const float* src, long long sB,
                       const float* offp, int C, int mode, int br) {
        dim3 g((HW2 + 255) / 256, 18, (C + 63) / 64);
        deform_im2col_k<<<g, 256, 0, st>>>(src, sB, offp, COLS(br),
                                           COLSH(br), COLSL(br), C, mode);
    };
    auto IM2COL = [&](cudaStream_t st, const float* src, long long sB, int C,
                      int H, int W, int KH, int KW, int stp, int pad,
                      int OH, int OW, int br) {
        dim3 g((OH * OW + 255) / 256, C * KH * KW, 2);
        im2col_g<<<g, 256, 0, st>>>(src, sB, COLS(br), C, H, W, KH, KW, stp, pad, OH, OW);
    };
    auto CONV18 = [&](cudaStream_t st, const float* in, long long inB,
                      const float* w, float* o, int br) {
        conv18_k<<<dim3(9, 16, 2), 256, 0, st>>>(in, inB, w, CPART(br), 512);
        reduce18_k<<<(2 * 18 * HW2 + 255) / 256, 256, 0, st>>>(CPART(br), o);
    };
    auto WBRANCH = [&](cudaStream_t st, const float* feat, const float* wa,
                       const float* wb, const float* wc, int Mc, int br) {
        IM2COL(st, feat, 177LL * HW2, 177, 48, 48, 5, 5, 2, 2, 24, 24, br);
        GEMMF(st, wa, COLS(br), WB1(br), 64, 576, 4425, 0, 4425LL * 576, 64LL * 576,
              nullptr, 1);
        IM2COL(st, WB1(br), 64LL * 576, 64, 24, 24, 5, 5, 2, 2, 12, 12, br);
        GEMMF(st, wb, COLS(br), WB2(br), 64, 144, 1600, 0, 1600LL * 144, 64LL * 144,
              nullptr, 1);
        IM2COL(st, WB2(br), 64LL * 144, 64, 12, 12, 3, 3, 2, 1, 6, 6, br);
        GEMMF(st, wc, COLS(br), WB3(br), Mc, 36, 576, 0, 576LL * 36,
              (long long)Mc * 36, nullptr, 0);
        int tot = 2 * Mc;
        mean36_k<<<(tot + 255) / 256, 256, 0, st>>>(WB3(br), FW(br), tot);
    };

    // ---- L0: hoisted weight splits + encoders ----
    for (int i = 0; i < 3; i++)
        convw_k<<<(DW + 255) / 256, 256, 0, sM>>>(defw[i], dwh + (long long)i * DW,
                                                  dwl + (long long)i * DW, DW);
    convw_k<<<(128 * 2304 + 255) / 256, 256, 0, sM>>>(s1w, s1h, s1l, 128 * 2304);
    GEMMA(sM, enc0_w, inp,             xenc, 64, HW2, 256, 0, imgStride, 64LL * HW2, enc0_b, 0);
    GEMMA(sM, enc1_w, inp + 256 * HW2, yenc, 64, HW2, 256, 0, imgStride, 64LL * HW2, enc1_b, 0);
    cudaEventRecord(eInit, sM);
    cudaStreamWaitEvent(sW0, eInit, 0);
    cudaStreamWaitEvent(sS1, eInit, 0);
    cudaStreamWaitEvent(sW1, eInit, 0);

    auto STSN = [&](cudaStream_t st, int br) {
        const float* imgA = (br == 0) ? inp : inp + 256 * HW2;
        const float* imgB = inp + 256 * HW2;
        int tot = 2 * 512 * HW2;
        concat_k<<<(tot + 255) / 256, 256, 0, st>>>(imgA, imgB, F512A(br), imgStride);
        float* cur = F512A(br); float* oth = F512B(br);
        for (int i = 0; i < 3; i++) {
            CONV18(st, cur, 512LL * HW2, offw[i], OFF(br), br);
            DIM2COL(st, cur, 512LL * HW2, OFF(br), 512, 1, br);
            GEMMTB(st, dwh + (long long)i * DW, dwl + (long long)i * DW,
                   COLSH(br), COLSL(br), oth, 512, HW2, 4608,
                   0, 4608LL * HW2, 512LL * HW2, 0);
            float* t = cur; cur = oth; oth = t;
        }
        CONV18(st, cur, 512LL * HW2, offw[3], OFF(br), br);
    };

    auto WEIGHT = [&](cudaStream_t st, int br) {
        const float* Ra = R0 + (br == 0 ? 0 : 64 * HW2);
        const float* Tb = T0 + 64 * HW2;
        const float* eA = (br == 0) ? xenc : yenc;
        const float* eB = yenc;
        int tot = 2 * 49 * HW2;
        corr_k<<<(tot + 255) / 256, 256, 0, st>>>(Ra, Tb, F177(br));
        tot = 2 * 64 * HW2;
        pack_k<<<(tot + 255) / 256, 256, 0, st>>>(eA, eB, F177(br));
        WBRANCH(st, F177(br), w0a, w0b, w0c, 177, br);
        tot = 2 * 177 * 1593;
        mkw_k<<<(tot + 255) / 256, 256, 0, st>>>(FW(br), wx_w, wx_b, ADW(br), 177, 1593, tot);
        DIM2COL(st, F177(br), 177LL * HW2, nullptr, 177, 0, br);
        GEMMF(st, ADW(br), COLS(br), F177B(br), 177, HW2, 1593,
              177LL * 1593, 1593LL * HW2, 177LL * HW2, nullptr, 1);
        WBRANCH(st, F177B(br), w1a, w1b, w1c, 256, br);
        tot = 2 * 256 * 2304;
        mkw_k<<<(tot + 255) / 256, 256, 0, st>>>(FW(br), wxf_w, wxf_b, ADW(br), 256, 2304, tot);
        convw_k<<<(2 * 256 * 2304 + 255) / 256, 256, 0, st>>>(ADW(br), AWH(br), AWL(br),
                                                              2 * 256 * 2304);
    };

    auto TAIL = [&](cudaStream_t st, int br, float* gdef, float* gsw) {
        const float* imgA = (br == 0) ? inp : inp + 256 * HW2;
        DIM2COL(st, imgA, imgStride, OFF(br), 256, 1, br);
        GEMMTB(st, AWH(br), AWL(br), COLSH(br), COLSL(br), gdef, 256, HW2, 2304,
               256LL * 2304, 2304LL * HW2, 256LL * HW2, 0);
        DIM2COL(st, gdef, 256LL * HW2, nullptr, 256, 1, br);
        GEMMTB(st, s1h, s1l, COLSH(br), COLSL(br), S1O(br), 128, HW2, 2304,
               0, 2304LL * HW2, 128LL * HW2, 1);
        DIM2COL(st, S1O(br), 128LL * HW2, nullptr, 128, 0, br);
        GEMMA(st, s2w, COLS(br), S2O(br), 64, HW2, 1152,
              0, 1152LL * HW2, 64LL * HW2, nullptr, 1);
        conv3x3_direct<<<dim3(9, 1, 2), 256, 0, st>>>(S2O(br), 64LL * HW2, s3w, gsw,
                                                      (long long)HW2, 64, 1);
    };

    // branch 0: stsn on L0 (sM), weight on sW0
    STSN(sM, 0);
    WEIGHT(sW0, 0);
    cudaEventRecord(eW0, sW0);
    cudaStreamWaitEvent(sM, eW0, 0);
    TAIL(sM, 0, def0, swa);

    // branch 1: stsn on sS1, weight on sW1
    STSN(sS1, 1);
    WEIGHT(sW1, 1);
    cudaEventRecord(eW1, sW1);
    cudaStreamWaitEvent(sS1, eW1, 0);
    TAIL(sS1, 1, def1, swb);
    cudaEventRecord(eB1, sS1);
    cudaStreamWaitEvent(sM, eB1, 0);

    {
        int tot = 2 * 256 * HW2;
        final_k<<<(tot + 255) / 256, 256, 0, sM>>>(def0, def1, swa, swb, out, tot);
    }

    cudaEventDestroy(eInit);
    cudaEventDestroy(eW0);
    cudaEventDestroy(eW1);
    cudaEventDestroy(eB1);
    cudaStreamDestroy(sW0);
    cudaStreamDestroy(sS1);
    cudaStreamDestroy(sW1);
}

// round 12
// speedup vs baseline: 1.0081x; 1.0081x over previous
#include <cuda_runtime.h>
#include <cuda_bf16.h>
#include <math.h>

#define HW2 2304
#define HH 48
#define WW 48

typedef unsigned int u32;
typedef unsigned short u16;

// ---------------- device scratch (no allocations allowed; [2] = per-branch) ----------------
__device__ float g_xenc  [2*64 *HW2];
__device__ float g_yenc  [2*64 *HW2];
__device__ float g_f512a [2][2*512*HW2];
__device__ float g_f512b [2][2*512*HW2];
__device__ float g_cols  [2][2*1600*HW2];
__device__ u16   g_colsh [2][2*4608*HW2];
__device__ u16   g_colsl [2][2*4608*HW2];
__device__ u16   g_awh   [2][2*256*2304];
__device__ u16   g_awl   [2][2*256*2304];
__device__ u16   g_dwh   [3*512*4608];
__device__ u16   g_dwl   [3*512*4608];
__device__ u16   g_s1h   [128*2304];
__device__ u16   g_s1l   [128*2304];
__device__ float g_offb  [2][2*18 *HW2];
__device__ float g_cpart [2][16*2*18*HW2];
__device__ float g_f177  [2][2*177*HW2];
__device__ float g_f177b [2][2*177*HW2];
__device__ float g_wb1   [2][2*64*576];
__device__ float g_wb2   [2][2*64*144];
__device__ float g_wb3   [2][2*256*36];
__device__ float g_fwb   [2][2*256];
__device__ float g_adw   [2][2*256*HW2];
__device__ float g_def0  [2*256*HW2];
__device__ float g_def1  [2*256*HW2];
__device__ float g_s1o   [2][2*128*HW2];
__device__ float g_s2o   [2][2*64*HW2];
__device__ float g_swa   [2*HW2];
__device__ float g_swb   [2*HW2];

// ---------------- helpers ----------------
__device__ __forceinline__ void split16(float x, u16& h, u16& l)
{
    __nv_bfloat16 xh = __float2bfloat16(x);
    h = __bfloat16_as_ushort(xh);
    l = __bfloat16_as_ushort(__float2bfloat16(x - __bfloat162float(xh)));
}

__global__ void convw_k(const float* __restrict__ src, u16* __restrict__ h,
                        u16* __restrict__ l, int n)
{
    int i = blockIdx.x * 256 + threadIdx.x;
    if (i >= n) return;
    u16 hh, ll;
    split16(src[i], hh, ll);
    h[i] = hh; l[i] = ll;
}

#define MMA16816(c, a, b0v, b1v) \
    asm volatile("mma.sync.aligned.m16n8k16.row.col.f32.bf16.bf16.f32 " \
        "{%0,%1,%2,%3},{%4,%5,%6,%7},{%8,%9},{%0,%1,%2,%3};" \
        : "+f"((c)[0]), "+f"((c)[1]), "+f"((c)[2]), "+f"((c)[3]) \
        : "r"((a)[0]), "r"((a)[1]), "r"((a)[2]), "r"((a)[3]), \
          "r"(b0v), "r"(b1v))

// ---------------- bf16x3 split tensor-core GEMM, pre-split inputs (R8 order) ----------------
__global__ __launch_bounds__(256)
void gemm_bf3b(const u16* __restrict__ Ah, const u16* __restrict__ Al,
               const u16* __restrict__ Bh, const u16* __restrict__ Bl,
               float* __restrict__ C, int M, int N, int K,
               long long sA, long long sB, long long sC, int relu)
{
    Ah += (long long)blockIdx.z * sA;
    Al += (long long)blockIdx.z * sA;
    Bh += (long long)blockIdx.z * sB;
    Bl += (long long)blockIdx.z * sB;
    C  += (long long)blockIdx.z * sC;

    __shared__ u32 sAh[2][128][13];
    __shared__ u32 sAl[2][128][13];
    __shared__ u32 sBh[2][64][13];
    __shared__ u32 sBl[2][64][13];

    const int tid = threadIdx.x;
    const int lane = tid & 31, warp = tid >> 5;
    const int wm = warp >> 1, wn = warp & 1;
    const int m0 = blockIdx.y * 128, n0 = blockIdx.x * 64;

    const int arow = tid >> 1, ahalf = tid & 1;
    const u16* ApH = Ah + (long long)(m0 + arow) * K + ahalf * 8;
    const u16* ApL = Al + (long long)(m0 + arow) * K + ahalf * 8;

    const int bw = warp;
    const int bn = lane * 2;
    const u16* BpH = Bh + n0 + bn;
    const u16* BpL = Bl + n0 + bn;

    float acc[2][4][4];
#pragma unroll
    for (int mt = 0; mt < 2; mt++)
#pragma unroll
        for (int nt = 0; nt < 4; nt++)
#pragma unroll
            for (int i = 0; i < 4; i++) acc[mt][nt][i] = 0.f;

    uint4 lah, lal;
    u32 lbh0, lbh1, lbl0, lbl1;

    lah = *(const uint4*)ApH;
    lal = *(const uint4*)ApL;
    lbh0 = *(const u32*)(BpH + (long long)(2 * bw) * N);
    lbh1 = *(const u32*)(BpH + (long long)(2 * bw + 1) * N);
    lbl0 = *(const u32*)(BpL + (long long)(2 * bw) * N);
    lbl1 = *(const u32*)(BpL + (long long)(2 * bw + 1) * N);
    {
        sAh[0][arow][ahalf*4+0] = lah.x; sAh[0][arow][ahalf*4+1] = lah.y;
        sAh[0][arow][ahalf*4+2] = lah.z; sAh[0][arow][ahalf*4+3] = lah.w;
        sAl[0][arow][ahalf*4+0] = lal.x; sAl[0][arow][ahalf*4+1] = lal.y;
        sAl[0][arow][ahalf*4+2] = lal.z; sAl[0][arow][ahalf*4+3] = lal.w;
        sBh[0][bn  ][bw] = __byte_perm(lbh0, lbh1, 0x5410);
        sBh[0][bn+1][bw] = __byte_perm(lbh0, lbh1, 0x7632);
        sBl[0][bn  ][bw] = __byte_perm(lbl0, lbl1, 0x5410);
        sBl[0][bn+1][bw] = __byte_perm(lbl0, lbl1, 0x7632);
    }
    __syncthreads();

    const int ar = lane >> 2, ac = lane & 3;
    int buf = 0;
    for (int k0 = 0; k0 < K; k0 += 16) {
        const bool has = (k0 + 16) < K;
        if (has) {
            lah = *(const uint4*)(ApH + k0 + 16);
            lal = *(const uint4*)(ApL + k0 + 16);
            const long long r0 = (long long)(k0 + 16 + 2 * bw) * N;
            lbh0 = *(const u32*)(BpH + r0);
            lbh1 = *(const u32*)(BpH + r0 + N);
            lbl0 = *(const u32*)(BpL + r0);
            lbl1 = *(const u32*)(BpL + r0 + N);
        }

        u32 ah[2][4], al[2][4];
#pragma unroll
        for (int mt = 0; mt < 2; mt++) {
            int r = wm * 32 + mt * 16 + ar;
            ah[mt][0] = sAh[buf][r][ac];         al[mt][0] = sAl[buf][r][ac];
            ah[mt][1] = sAh[buf][r + 8][ac];     al[mt][1] = sAl[buf][r + 8][ac];
            ah[mt][2] = sAh[buf][r][ac + 4];     al[mt][2] = sAl[buf][r][ac + 4];
            ah[mt][3] = sAh[buf][r + 8][ac + 4]; al[mt][3] = sAl[buf][r + 8][ac + 4];
        }
#pragma unroll
        for (int nt = 0; nt < 4; nt++) {
            int nr = wn * 32 + nt * 8 + ar;
            u32 bh0 = sBh[buf][nr][ac], bh1 = sBh[buf][nr][ac + 4];
            u32 bl0 = sBl[buf][nr][ac], bl1 = sBl[buf][nr][ac + 4];
#pragma unroll
            for (int mt = 0; mt < 2; mt++) {
                MMA16816(acc[mt][nt], ah[mt], bh0, bh1);
                MMA16816(acc[mt][nt], ah[mt], bl0, bl1);
                MMA16816(acc[mt][nt], al[mt], bh0, bh1);
            }
        }

        if (has) {
            int nb = buf ^ 1;
            sAh[nb][arow][ahalf*4+0] = lah.x; sAh[nb][arow][ahalf*4+1] = lah.y;
            sAh[nb][arow][ahalf*4+2] = lah.z; sAh[nb][arow][ahalf*4+3] = lah.w;
            sAl[nb][arow][ahalf*4+0] = lal.x; sAl[nb][arow][ahalf*4+1] = lal.y;
            sAl[nb][arow][ahalf*4+2] = lal.z; sAl[nb][arow][ahalf*4+3] = lal.w;
            sBh[nb][bn  ][bw] = __byte_perm(lbh0, lbh1, 0x5410);
            sBh[nb][bn+1][bw] = __byte_perm(lbh0, lbh1, 0x7632);
            sBl[nb][bn  ][bw] = __byte_perm(lbl0, lbl1, 0x5410);
            sBl[nb][bn+1][bw] = __byte_perm(lbl0, lbl1, 0x7632);
        }
        __syncthreads();
        buf ^= 1;
    }

#pragma unroll
    for (int mt = 0; mt < 2; mt++) {
        int r = m0 + wm * 32 + mt * 16 + ar;
#pragma unroll
        for (int nt = 0; nt < 4; nt++) {
            int c = n0 + wn * 32 + nt * 8 + ac * 2;
            float2 v0 = make_float2(acc[mt][nt][0], acc[mt][nt][1]);
            float2 v1 = make_float2(acc[mt][nt][2], acc[mt][nt][3]);
            if (relu) {
                v0.x = fmaxf(v0.x, 0.f); v0.y = fmaxf(v0.y, 0.f);
                v1.x = fmaxf(v1.x, 0.f); v1.y = fmaxf(v1.y, 0.f);
            }
            *(float2*)&C[(long long)r * N + c] = v0;
            *(float2*)&C[(long long)(r + 8) * N + c] = v1;
        }
    }
}

// ---------------- aligned fast fp32 GEMM ----------------
template<int RN>
__global__ __launch_bounds__(256)
void gemm_al(const float* __restrict__ A, const float* __restrict__ B,
             float* __restrict__ C, int M, int N, int K,
             long long sA, long long sB, long long sC,
             const float* __restrict__ bias, int relu)
{
    constexpr int TN = 16 * RN;
    A += (long long)blockIdx.z * sA;
    B += (long long)blockIdx.z * sB;
    C += (long long)blockIdx.z * sC;

    __shared__ float As[2][16][68];
    __shared__ float Bs[2][16][TN];

    const int tid = threadIdx.x;
    const int tx = tid & 15, ty = tid >> 4;
    const int m0 = blockIdx.y * 64, n0 = blockIdx.x * TN;

    const int ar = tid >> 2;
    const int ak = (tid & 3) * 4;
    const int bk = tid >> 4;
    const int bn = (tid & 15) * RN;

    const float* Ap = A + (long long)(m0 + ar) * K + ak;
    const float* Bp = B + (long long)bk * N + n0 + bn;

    float acc[4][RN];
#pragma unroll
    for (int i = 0; i < 4; i++)
#pragma unroll
        for (int j = 0; j < RN; j++) acc[i][j] = 0.f;

    {
        float4 av = *(const float4*)Ap;
        As[0][ak + 0][ar] = av.x; As[0][ak + 1][ar] = av.y;
        As[0][ak + 2][ar] = av.z; As[0][ak + 3][ar] = av.w;
#pragma unroll
        for (int h = 0; h < RN / 4; h++)
            *(float4*)&Bs[0][bk][bn + h * 4] = *(const float4*)(Bp + h * 4);
    }
    __syncthreads();

    int buf = 0;
    for (int k0 = 0; k0 < K; k0 += 16) {
        const bool has = (k0 + 16) < K;
        float4 la;
        float4 lbv[RN / 4];
        if (has) {
            la = *(const float4*)(Ap + k0 + 16);
#pragma unroll
            for (int h = 0; h < RN / 4; h++)
                lbv[h] = *(const float4*)(Bp + (long long)(k0 + 16) * N + h * 4);
        }

#pragma unroll
        for (int kk = 0; kk < 16; kk++) {
            float4 a4 = *(const float4*)&As[buf][kk][ty * 4];
            float a[4] = {a4.x, a4.y, a4.z, a4.w};
            float b[RN];
#pragma unroll
            for (int h = 0; h < RN / 4; h++) {
                float4 b4 = *(const float4*)&Bs[buf][kk][h * 64 + tx * 4];
                b[h * 4 + 0] = b4.x; b[h * 4 + 1] = b4.y;
                b[h * 4 + 2] = b4.z; b[h * 4 + 3] = b4.w;
            }
#pragma unroll
            for (int i = 0; i < 4; i++)
#pragma unroll
                for (int j = 0; j < RN; j++) acc[i][j] += a[i] * b[j];
        }

        if (has) {
            int nb = buf ^ 1;
            As[nb][ak + 0][ar] = la.x; As[nb][ak + 1][ar] = la.y;
            As[nb][ak + 2][ar] = la.z; As[nb][ak + 3][ar] = la.w;
#pragma unroll
            for (int h = 0; h < RN / 4; h++)
                *(float4*)&Bs[nb][bk][bn + h * 4] = lbv[h];
        }
        __syncthreads();
        buf ^= 1;
    }

#pragma unroll
    for (int i = 0; i < 4; i++) {
        int m = m0 + ty * 4 + i;
        float bv = bias ? bias[m] : 0.f;
#pragma unroll
        for (int h = 0; h < RN / 4; h++) {
            float4 v;
            v.x = acc[i][h * 4 + 0] + bv;
            v.y = acc[i][h * 4 + 1] + bv;
            v.z = acc[i][h * 4 + 2] + bv;
            v.w = acc[i][h * 4 + 3] + bv;
            if (relu) {
                v.x = fmaxf(v.x, 0.f); v.y = fmaxf(v.y, 0.f);
                v.z = fmaxf(v.z, 0.f); v.w = fmaxf(v.w, 0.f);
            }
            *(float4*)&C[(long long)m * N + n0 + h * 64 + tx * 4] = v;
        }
    }
}

// ---------------- fallback 64x64 GEMM (any shape) ----------------
__global__ void gemm64(const float* __restrict__ A, const float* __restrict__ B,
                       float* __restrict__ C, int M, int N, int K,
                       long long sA, long long sB, long long sC,
                       const float* __restrict__ bias, int relu)
{
    A += (long long)blockIdx.z * sA;
    B += (long long)blockIdx.z * sB;
    C += (long long)blockIdx.z * sC;
    __shared__ float As[16][64];
    __shared__ float Bs[16][68];
    int tx = threadIdx.x, ty = threadIdx.y;
    int tid = ty * 16 + tx;
    int m0 = blockIdx.y * 64, n0 = blockIdx.x * 64;
    int mA = tid >> 2, kA = (tid & 3) * 4;
    int kB = tid >> 4, nB = (tid & 15) * 4;
    float acc[4][4];
#pragma unroll
    for (int i = 0; i < 4; i++)
#pragma unroll
        for (int j = 0; j < 4; j++) acc[i][j] = 0.f;

    for (int k0 = 0; k0 < K; k0 += 16) {
#pragma unroll
        for (int i = 0; i < 4; i++) {
            int k = k0 + kA + i;
            As[kA + i][mA] = (m0 + mA < M && k < K) ? A[(long long)(m0 + mA) * K + k] : 0.f;
        }
#pragma unroll
        for (int i = 0; i < 4; i++) {
            int n = n0 + nB + i;
            Bs[kB][nB + i] = (k0 + kB < K && n < N) ? B[(long long)(k0 + kB) * N + n] : 0.f;
        }
        __syncthreads();
#pragma unroll
        for (int kk = 0; kk < 16; kk++) {
            float a[4], b[4];
#pragma unroll
            for (int i = 0; i < 4; i++) a[i] = As[kk][ty * 4 + i];
#pragma unroll
            for (int j = 0; j < 4; j++) b[j] = Bs[kk][tx * 4 + j];
#pragma unroll
            for (int i = 0; i < 4; i++)
#pragma unroll
                for (int j = 0; j < 4; j++) acc[i][j] += a[i] * b[j];
        }
        __syncthreads();
    }
#pragma unroll
    for (int i = 0; i < 4; i++) {
        int m = m0 + ty * 4 + i;
        if (m >= M) continue;
        float bv = bias ? bias[m] : 0.f;
#pragma unroll
        for (int j = 0; j < 4; j++) {
            int n = n0 + tx * 4 + j;
            if (n >= N) continue;
            float v = acc[i][j] + bv;
            if (relu) v = fmaxf(v, 0.f);
            C[(long long)m * N + n] = v;
        }
    }
}

// ---------------- 512->18 offset-head 3x3 conv ----------------
__global__ void conv18_k(const float* __restrict__ in, long long inB,
                         const float* __restrict__ w, float* __restrict__ part, int C)
{
    const int t = blockIdx.x, cc = blockIdx.y, b = blockIdx.z;
    const int tid = threadIdx.x;
    const int hw = t * 256 + tid;
    const int h = hw / WW, x = hw % WW;
    const int hf = (t * 256) / WW;

    __shared__ float sIn[4][9 * WW];
    __shared__ float sW[4][18 * 9];

    float acc[18];
#pragma unroll
    for (int o = 0; o < 18; o++) acc[o] = 0.f;

    const float* ib = in + (long long)b * inB + (long long)(cc * 32) * HW2;
    const int lr = h - (hf - 1);

    for (int cs = 0; cs < 32; cs += 4) {
        for (int i = tid; i < 4 * 9 * WW; i += 256) {
            int c = i / (9 * WW), r = i % (9 * WW);
            int row = hf - 1 + r / WW, col = r % WW;
            float v = 0.f;
            if (row >= 0 && row < HH) v = ib[(long long)(cs + c) * HW2 + row * WW + col];
            sIn[c][r] = v;
        }
        for (int i = tid; i < 4 * 162; i += 256) {
            int c = i / 162, r = i % 162;
            int o = r / 9, q = r % 9;
            sW[c][r] = w[((long long)o * C + (cc * 32 + cs + c)) * 9 + q];
        }
        __syncthreads();

#pragma unroll
        for (int c = 0; c < 4; c++) {
            float tap[9];
#pragma unroll
            for (int ki = 0; ki < 3; ki++)
#pragma unroll
                for (int kj = 0; kj < 3; kj++) {
                    int xx = x - 1 + kj;
                    float v = 0.f;
                    if (xx >= 0 && xx < WW) v = sIn[c][(lr - 1 + ki) * WW + xx];
                    tap[ki * 3 + kj] = v;
                }
#pragma unroll
            for (int o = 0; o < 18; o++) {
                float s = acc[o];
#pragma unroll
                for (int q = 0; q < 9; q++) s += sW[c][o * 9 + q] * tap[q];
                acc[o] = s;
            }
        }
        __syncthreads();
    }

    float* pp = part + ((long long)cc * 2 + b) * 18 * HW2;
#pragma unroll
    for (int o = 0; o < 18; o++) pp[(long long)o * HW2 + hw] = acc[o];
}

__global__ void reduce18_k(const float* __restrict__ part, float* __restrict__ out)
{
    int idx = blockIdx.x * 256 + threadIdx.x;
    if (idx >= 2 * 18 * HW2) return;
    int b = idx / (18 * HW2);
    int r = idx % (18 * HW2);
    float s = 0.f;
#pragma unroll
    for (int c = 0; c < 16; c++) s += part[((long long)c * 2 + b) * 18 * HW2 + r];
    out[(long long)b * 18 * HW2 + r] = s;
}

// ---------------- deformable (or plain) 3x3 s1 p1 im2col (zofs = channel-chunk offset) ----------------
__global__ void deform_im2col_k(const float* __restrict__ src, long long srcB,
                                const float* __restrict__ off,
                                float* __restrict__ colsF,
                                u16* __restrict__ colsH, u16* __restrict__ colsL,
                                int C, int mode, int zofs)
{
    int hw = blockIdx.x * 256 + threadIdx.x;
    if (hw >= HW2) return;
    int bq = blockIdx.y;
    int b = bq / 9, q = bq % 9;
    int ki = q / 3, kj = q % 3;
    int h = hw / WW, w = hw % WW;
    const float* sb = src + (long long)b * srcB;
    long long cbase = (long long)b * C * 9 * HW2;
    int c0 = (blockIdx.z + zofs) * 64;
    int c1 = c0 + 64; if (c1 > C) c1 = C;

    float w00, w01, w10, w11;
    int i00, i01, i10, i11;
    if (off == nullptr) {
        int y = h - 1 + ki, x = w - 1 + kj;
        bool vin = (y >= 0 && y < HH && x >= 0 && x < WW);
        w00 = vin ? 1.f : 0.f; w01 = w10 = w11 = 0.f;
        i00 = vin ? (y * WW + x) : 0; i01 = i10 = i11 = 0;
    } else {
        float py = (float)(h - 1 + ki) + off[((long long)b * 18 + 2 * q) * HW2 + hw];
        float px = (float)(w - 1 + kj) + off[((long long)b * 18 + 2 * q + 1) * HW2 + hw];
        float fy = floorf(py), fx = floorf(px);
        float ay = py - fy, ax = px - fx;
        int y0 = (int)fy, x0 = (int)fx;
        int y1 = y0 + 1, x1 = x0 + 1;
        bool by0 = (y0 >= 0 && y0 < HH), by1 = (y1 >= 0 && y1 < HH);
        bool bx0 = (x0 >= 0 && x0 < WW), bx1 = (x1 >= 0 && x1 < WW);
        int yc0 = min(max(y0, 0), HH - 1), yc1 = min(max(y1, 0), HH - 1);
        int xc0 = min(max(x0, 0), WW - 1), xc1 = min(max(x1, 0), WW - 1);
        w00 = (by0 && bx0) ? (1.f - ay) * (1.f - ax) : 0.f;
        w01 = (by0 && bx1) ? (1.f - ay) * ax : 0.f;
        w10 = (by1 && bx0) ? ay * (1.f - ax) : 0.f;
        w11 = (by1 && bx1) ? ay * ax : 0.f;
        i00 = yc0 * WW + xc0; i01 = yc0 * WW + xc1;
        i10 = yc1 * WW + xc0; i11 = yc1 * WW + xc1;
    }

    for (int c = c0; c < c1; c++) {
        const float* s = sb + (long long)c * HW2;
        float v = w00 * s[i00] + w01 * s[i01] + w10 * s[i10] + w11 * s[i11];
        long long idx = cbase + ((long long)c * 9 + q) * HW2 + hw;
        if (mode == 0) {
            colsF[idx] = v;
        } else {
            u16 hh, ll;
            split16(v, hh, ll);
            colsH[idx] = hh; colsL[idx] = ll;
        }
    }
}

// ---------------- generic strided im2col ----------------
__global__ void im2col_g(const float* __restrict__ src, long long srcB,
                         float* __restrict__ cols,
                         int C, int H, int W, int KH, int KW,
                         int stride, int pad, int OH, int OW)
{
    int ohw = blockIdx.x * 256 + threadIdx.x;
    int OHW = OH * OW;
    if (ohw >= OHW) return;
    int row = blockIdx.y;
    int b = blockIdx.z;
    int kk = row % (KH * KW);
    int c = row / (KH * KW);
    int kh = kk / KW, kw = kk % KW;
    int oh = ohw / OW, ow = ohw % OW;
    int ih = oh * stride - pad + kh;
    int iw = ow * stride - pad + kw;
    float v = 0.f;
    if (ih >= 0 && ih < H && iw >= 0 && iw < W)
        v = src[(long long)b * srcB + ((long long)c * H + ih) * W + iw];
    cols[((long long)b * C * KH * KW + row) * OHW + ohw] = v;
}

// ---------------- direct 3x3 conv (tiny s3: 64->1) ----------------
__global__ void conv3x3_direct(const float* __restrict__ in, long long inB,
                               const float* __restrict__ w, float* __restrict__ out,
                               long long outB, int C, int relu)
{
    int hw = blockIdx.x * 256 + threadIdx.x;
    if (hw >= HW2) return;
    int o = blockIdx.y, b = blockIdx.z;
    int h = hw / WW, x = hw % WW;
    const float* ib = in + (long long)b * inB;
    const float* wo = w + (long long)o * C * 9;
    float acc = 0.f;
    for (int c = 0; c < C; c++) {
        const float* ic = ib + (long long)c * HW2;
        const float* wc = wo + c * 9;
#pragma unroll
        for (int kh = 0; kh < 3; kh++) {
            int ih = h + kh - 1;
            if (ih < 0 || ih >= HH) continue;
#pragma unroll
            for (int kw = 0; kw < 3; kw++) {
                int iw = x + kw - 1;
                if (iw < 0 || iw >= WW) continue;
                acc += ic[ih * WW + iw] * wc[kh * 3 + kw];
            }
        }
    }
    if (relu) acc = fmaxf(acc, 0.f);
    out[(long long)b * outB + (long long)o * HW2 + hw] = acc;
}

// ---------------- elementwise kernels ----------------
__global__ void concat_k(const float* __restrict__ a, const float* __restrict__ b_,
                         float* __restrict__ o, long long imgStride)
{
    int idx = blockIdx.x * 256 + threadIdx.x;
    if (idx >= 2 * 512 * HW2) return;
    int bb = idx / (512 * HW2);
    int c = (idx / HW2) % 512;
    int hw = idx % HW2;
    float v = (c < 256) ? a[bb * imgStride + (long long)c * HW2 + hw]
                        : b_[bb * imgStride + (long long)(c - 256) * HW2 + hw];
    o[idx] = v;
}

__global__ void corr_k(const float* __restrict__ Ra, const float* __restrict__ Tb,
                       float* __restrict__ f177)
{
    int idx = blockIdx.x * 256 + threadIdx.x;
    if (idx >= 2 * 49 * HW2) return;
    int b = idx / (49 * HW2);
    int q = (idx / HW2) % 49;
    int hw = idx % HW2;
    int h = hw / WW, w = hw % WW;
    int dy = 2 * ((q / 7) - 3), dx = 2 * ((q % 7) - 3);
    int hh = h + dy, ww = w + dx;
    float s = 0.f;
    if (hh >= 0 && hh < HH && ww >= 0 && ww < WW) {
        const float* a = Ra + (long long)b * (2 * 64 * HW2) + hw;
        const float* bp = Tb + (long long)b * (2 * 64 * HW2) + hh * WW + ww;
        for (int c = 0; c < 64; c++) s += a[c * HW2] * bp[c * HW2];
    }
    f177[((long long)b * 177 + q) * HW2 + hw] = s * (1.f / 64.f);
}

__global__ void pack_k(const float* __restrict__ eA, const float* __restrict__ eB,
                       float* __restrict__ f177)
{
    int idx = blockIdx.x * 256 + threadIdx.x;
    if (idx >= 2 * 64 * HW2) return;
    int b = idx / (64 * HW2);
    int c = (idx / HW2) % 64;
    int hw = idx % HW2;
    f177[((long long)b * 177 + 49 + c) * HW2 + hw] = eA[idx];
    f177[((long long)b * 177 + 113 + c) * HW2 + hw] = eB[idx];
}

__global__ void mean36_k(const float* __restrict__ in, float* __restrict__ fw, int total)
{
    int i = blockIdx.x * 256 + threadIdx.x;
    if (i >= total) return;
    float s = 0.f;
#pragma unroll
    for (int j = 0; j < 36; j++) s += in[i * 36 + j];
    fw[i] = s * (1.f / 36.f);
}

__global__ void mkw_k(const float* __restrict__ fw, const float* __restrict__ Wt,
                      const float* __restrict__ Bi, float* __restrict__ adw,
                      int M, int Kc, int total)
{
    int idx = blockIdx.x * 256 + threadIdx.x;
    if (idx >= total) return;
    int b = idx / (M * Kc);
    int r = idx - b * M * Kc;
    int o = r / Kc;
    adw[idx] = fw[b * M + o] * Wt[r] + Bi[r];
}

__global__ void final_k(const float* __restrict__ d0, const float* __restrict__ d1,
                        const float* __restrict__ s0p, const float* __restrict__ s1p,
                        float* __restrict__ out, int total)
{
    int idx = blockIdx.x * 256 + threadIdx.x;
    if (idx >= total) return;
    int b = idx / (256 * HW2);
    int hw = idx % HW2;
    float s0 = s0p[b * HW2 + hw];
    float s1 = s1p[b * HW2 + hw];
    const float eps = 1e-8f;
    float wx = (s0 * s1) / (fmaxf(fabsf(s0), eps) * fmaxf(fabsf(s1), eps));
    float wy = (s1 * s1) / (fmaxf(fabsf(s1), eps) * fmaxf(fabsf(s1), eps));
    float mx = fmaxf(wx, wy);
    float e0 = expf(wx - mx), e1 = expf(wy - mx);
    float inv = 1.f / (e0 + e1);
    out[idx] = d0[idx] * (e0 * inv) + d1[idx] * (e1 * inv);
}

// ---------------- host orchestration (4-lane overlap + race-free TAIL pipelining) ----------------
extern "C" void kernel_launch(void* const* d_in, const int* in_sizes, int n_in,
                              void* d_out, int out_size)
{
    (void)in_sizes; (void)n_in; (void)out_size;
    const float* R0     = (const float*)d_in[0];
    const float* T0     = (const float*)d_in[1];
    const float* inp    = (const float*)d_in[2];
    const float* enc0_w = (const float*)d_in[3];
    const float* enc0_b = (const float*)d_in[4];
    const float* enc1_w = (const float*)d_in[5];
    const float* enc1_b = (const float*)d_in[6];
    const float* offw[4] = {(const float*)d_in[7], (const float*)d_in[8],
                            (const float*)d_in[9], (const float*)d_in[10]};
    const float* defw[3] = {(const float*)d_in[11], (const float*)d_in[12],
                            (const float*)d_in[13]};
    const float* w0a = (const float*)d_in[14];
    const float* w0b = (const float*)d_in[15];
    const float* w0c = (const float*)d_in[16];
    const float* w1a = (const float*)d_in[17];
    const float* w1b = (const float*)d_in[18];
    const float* w1c = (const float*)d_in[19];
    const float* wx_w  = (const float*)d_in[20];
    const float* wx_b  = (const float*)d_in[21];
    const float* wxf_w = (const float*)d_in[22];
    const float* wxf_b = (const float*)d_in[23];
    const float* s1w = (const float*)d_in[24];
    const float* s2w = (const float*)d_in[25];
    const float* s3w = (const float*)d_in[26];
    float* out = (float*)d_out;

    float *xenc, *yenc, *def0, *def1, *swa, *swb;
    float *f512aP, *f512bP, *colsP, *offP, *cpartP, *f177P, *f177bP;
    float *wb1P, *wb2P, *wb3P, *fwP, *adwP, *s1oP, *s2oP;
    u16 *colshP, *colslP, *awhP, *awlP, *dwh, *dwl, *s1h, *s1l;
    cudaGetSymbolAddress((void**)&xenc,   g_xenc);
    cudaGetSymbolAddress((void**)&yenc,   g_yenc);
    cudaGetSymbolAddress((void**)&f512aP, g_f512a);
    cudaGetSymbolAddress((void**)&f512bP, g_f512b);
    cudaGetSymbolAddress((void**)&colsP,  g_cols);
    cudaGetSymbolAddress((void**)&colshP, g_colsh);
    cudaGetSymbolAddress((void**)&colslP, g_colsl);
    cudaGetSymbolAddress((void**)&awhP,   g_awh);
    cudaGetSymbolAddress((void**)&awlP,   g_awl);
    cudaGetSymbolAddress((void**)&dwh,    g_dwh);
    cudaGetSymbolAddress((void**)&dwl,    g_dwl);
    cudaGetSymbolAddress((void**)&s1h,    g_s1h);
    cudaGetSymbolAddress((void**)&s1l,    g_s1l);
    cudaGetSymbolAddress((void**)&offP,   g_offb);
    cudaGetSymbolAddress((void**)&cpartP, g_cpart);
    cudaGetSymbolAddress((void**)&f177P,  g_f177);
    cudaGetSymbolAddress((void**)&f177bP, g_f177b);
    cudaGetSymbolAddress((void**)&wb1P,   g_wb1);
    cudaGetSymbolAddress((void**)&wb2P,   g_wb2);
    cudaGetSymbolAddress((void**)&wb3P,   g_wb3);
    cudaGetSymbolAddress((void**)&fwP,    g_fwb);
    cudaGetSymbolAddress((void**)&adwP,   g_adw);
    cudaGetSymbolAddress((void**)&def0,   g_def0);
    cudaGetSymbolAddress((void**)&def1,   g_def1);
    cudaGetSymbolAddress((void**)&s1oP,   g_s1o);
    cudaGetSymbolAddress((void**)&s2oP,   g_s2o);
    cudaGetSymbolAddress((void**)&swa,    g_swa);
    cudaGetSymbolAddress((void**)&swb,    g_swb);

    auto F512A = [&](int br){ return f512aP + (long long)br * (2*512*HW2); };
    auto F512B = [&](int br){ return f512bP + (long long)br * (2*512*HW2); };
    auto COLS  = [&](int br){ return colsP  + (long long)br * (2*1600*HW2); };
    auto COLSH = [&](int br){ return colshP + (long long)br * (2LL*4608*HW2); };
    auto COLSL = [&](int br){ return colslP + (long long)br * (2LL*4608*HW2); };
    auto AWH   = [&](int br){ return awhP   + (long long)br * (2*256*2304); };
    auto AWL   = [&](int br){ return awlP   + (long long)br * (2*256*2304); };
    auto OFF   = [&](int br){ return offP   + (long long)br * (2*18*HW2); };
    auto CPART = [&](int br){ return cpartP + (long long)br * (16LL*2*18*HW2); };
    auto F177  = [&](int br){ return f177P  + (long long)br * (2*177*HW2); };
    auto F177B = [&](int br){ return f177bP + (long long)br * (2*177*HW2); };
    auto WB1   = [&](int br){ return wb1P + (long long)br * (2*64*576); };
    auto WB2   = [&](int br){ return wb2P + (long long)br * (2*64*144); };
    auto WB3   = [&](int br){ return wb3P + (long long)br * (2*256*36); };
    auto FW    = [&](int br){ return fwP  + (long long)br * (2*256); };
    auto ADW   = [&](int br){ return adwP + (long long)br * (2*256*HW2); };
    auto S1O   = [&](int br){ return s1oP + (long long)br * (2*128*HW2); };
    auto S2O   = [&](int br){ return s2oP + (long long)br * (2*64*HW2); };

    const long long imgStride = 2LL * 256 * HW2;
    const int DW = 512 * 4608;

    // same stream budget as R8 (3 extra streams)
    cudaStream_t sM = 0, sW0, sS1, sW1;
    cudaStreamCreateWithFlags(&sW0, cudaStreamNonBlocking);
    cudaStreamCreateWithFlags(&sS1, cudaStreamNonBlocking);
    cudaStreamCreateWithFlags(&sW1, cudaStreamNonBlocking);
    const int NEV = 16;
    cudaEvent_t ev[NEV];
    for (int i = 0; i < NEV; i++) cudaEventCreateWithFlags(&ev[i], cudaEventDisableTiming);
    int evi = 0;
    auto FORK = [&](cudaStream_t from, cudaStream_t to) {
        cudaEventRecord(ev[evi], from);
        cudaStreamWaitEvent(to, ev[evi], 0);
        evi++;
    };

    auto GEMMTB = [&](cudaStream_t st, const u16* Ah, const u16* Al,
                      const u16* Bh, const u16* Bl, float* C,
                      int M, int N, int K,
                      long long sA, long long sB, long long sC, int relu) {
        gemm_bf3b<<<dim3(N / 64, M / 128, 2), 256, 0, st>>>(Ah, Al, Bh, Bl,
                                                            C, M, N, K, sA, sB, sC, relu);
    };
    auto GEMMA = [&](cudaStream_t st, const float* A, const float* Bm, float* C,
                     int M, int N, int K, long long sA, long long sB, long long sC,
                     const float* bias, int relu) {
        gemm_al<4><<<dim3(N / 64, M / 64, 2), 256, 0, st>>>(A, Bm, C, M, N, K,
                                                            sA, sB, sC, bias, relu);
    };
    auto GEMMF = [&](cudaStream_t st, const float* A, const float* Bm, float* C,
                     int M, int N, int K, long long sA, long long sB, long long sC,
                     const float* bias, int relu) {
        dim3 g((N + 63) / 64, (M + 63) / 64, 2);
        gemm64<<<g, dim3(16, 16), 0, st>>>(A, Bm, C, M, N, K, sA, sB, sC, bias, relu);
    };
    auto DIM2COL = [&](cudaStream_t st, const float* src, long long sB,
                       const float* offp, int C, int mode, int br, int zofs, int zcnt) {
        dim3 g((HW2 + 255) / 256, 18, zcnt);
        deform_im2col_k<<<g, 256, 0, st>>>(src, sB, offp, COLS(br),
                                           COLSH(br), COLSL(br), C, mode, zofs);
    };
    auto IM2COL = [&](cudaStream_t st, const float* src, long long sB, int C,
                      int H, int W, int KH, int KW, int stp, int pad,
                      int OH, int OW, int br) {
        dim3 g((OH * OW + 255) / 256, C * KH * KW, 2);
        im2col_g<<<g, 256, 0, st>>>(src, sB, COLS(br), C, H, W, KH, KW, stp, pad, OH, OW);
    };
    auto CONV18 = [&](cudaStream_t st, const float* in, long long inB,
                      const float* w, float* o, int br) {
        conv18_k<<<dim3(9, 16, 2), 256, 0, st>>>(in, inB, w, CPART(br), 512);
        reduce18_k<<<(2 * 18 * HW2 + 255) / 256, 256, 0, st>>>(CPART(br), o);
    };
    auto WBRANCH = [&](cudaStream_t st, const float* feat, const float* wa,
                       const float* wb, const float* wc, int Mc, int br) {
        IM2COL(st, feat, 177LL * HW2, 177, 48, 48, 5, 5, 2, 2, 24, 24, br);
        GEMMF(st, wa, COLS(br), WB1(br), 64, 576, 4425, 0, 4425LL * 576, 64LL * 576,
              nullptr, 1);
        IM2COL(st, WB1(br), 64LL * 576, 64, 24, 24, 5, 5, 2, 2, 12, 12, br);
        GEMMF(st, wb, COLS(br), WB2(br), 64, 144, 1600, 0, 1600LL * 144, 64LL * 144,
              nullptr, 1);
        IM2COL(st, WB2(br), 64LL * 144, 64, 12, 12, 3, 3, 2, 1, 6, 6, br);
        GEMMF(st, wc, COLS(br), WB3(br), Mc, 36, 576, 0, 576LL * 36,
              (long long)Mc * 36, nullptr, 0);
        int tot = 2 * Mc;
        mean36_k<<<(tot + 255) / 256, 256, 0, st>>>(WB3(br), FW(br), tot);
    };

    // ---- init: hoisted weight splits + encoders ----
    for (int i = 0; i < 3; i++)
        convw_k<<<(DW + 255) / 256, 256, 0, sM>>>(defw[i], dwh + (long long)i * DW,
                                                  dwl + (long long)i * DW, DW);
    convw_k<<<(128 * 2304 + 255) / 256, 256, 0, sM>>>(s1w, s1h, s1l, 128 * 2304);
    GEMMA(sM, enc0_w, inp,             xenc, 64, HW2, 256, 0, imgStride, 64LL * HW2, enc0_b, 0);
    GEMMA(sM, enc1_w, inp + 256 * HW2, yenc, 64, HW2, 256, 0, imgStride, 64LL * HW2, enc1_b, 0);
    {
        cudaEventRecord(ev[evi], sM);
        cudaStreamWaitEvent(sW0, ev[evi], 0);
        cudaStreamWaitEvent(sS1, ev[evi], 0);
        cudaStreamWaitEvent(sW1, ev[evi], 0);
        evi++;
    }

    // STSN: R8-identical serial chain
    auto STSN = [&](cudaStream_t st, int br) {
        const float* imgA = (br == 0) ? inp : inp + 256 * HW2;
        const float* imgB = inp + 256 * HW2;
        int tot = 2 * 512 * HW2;
        concat_k<<<(tot + 255) / 256, 256, 0, st>>>(imgA, imgB, F512A(br), imgStride);
        float* cur = F512A(br); float* oth = F512B(br);
        for (int i = 0; i < 3; i++) {
            CONV18(st, cur, 512LL * HW2, offw[i], OFF(br), br);
            DIM2COL(st, cur, 512LL * HW2, OFF(br), 512, 1, br, 0, 8);
            GEMMTB(st, dwh + (long long)i * DW, dwl + (long long)i * DW,
                   COLSH(br), COLSL(br), oth, 512, HW2, 4608,
                   0, 4608LL * HW2, 512LL * HW2, 0);
            float* t = cur; cur = oth; oth = t;
        }
        CONV18(st, cur, 512LL * HW2, offw[3], OFF(br), br);
    };

    auto WEIGHT = [&](cudaStream_t st, int br) {
        const float* Ra = R0 + (br == 0 ? 0 : 64 * HW2);
        const float* Tb = T0 + 64 * HW2;
        const float* eA = (br == 0) ? xenc : yenc;
        const float* eB = yenc;
        int tot = 2 * 49 * HW2;
        corr_k<<<(tot + 255) / 256, 256, 0, st>>>(Ra, Tb, F177(br));
        tot = 2 * 64 * HW2;
        pack_k<<<(tot + 255) / 256, 256, 0, st>>>(eA, eB, F177(br));
        WBRANCH(st, F177(br), w0a, w0b, w0c, 177, br);
        tot = 2 * 177 * 1593;
        mkw_k<<<(tot + 255) / 256, 256, 0, st>>>(FW(br), wx_w, wx_b, ADW(br), 177, 1593, tot);
        DIM2COL(st, F177(br), 177LL * HW2, nullptr, 177, 0, br, 0, 3);
        GEMMF(st, ADW(br), COLS(br), F177B(br), 177, HW2, 1593,
              177LL * 1593, 1593LL * HW2, 177LL * HW2, nullptr, 1);
        WBRANCH(st, F177B(br), w1a, w1b, w1c, 256, br);
        tot = 2 * 256 * 2304;
        mkw_k<<<(tot + 255) / 256, 256, 0, st>>>(FW(br), wxf_w, wxf_b, ADW(br), 256, 2304, tot);
        convw_k<<<(2 * 256 * 2304 + 255) / 256, 256, 0, st>>>(ADW(br), AWH(br), AWL(br),
                                                              2 * 256 * 2304);
    };

    // TAIL: pipelined on (branch stream, idle weight stream), race-free
    auto TAIL = [&](cudaStream_t st, cudaStream_t sw, int br, float* gdef, float* gsw) {
        const float* imgA = (br == 0) ? inp : inp + 256 * HW2;
        DIM2COL(st, imgA, imgStride, OFF(br), 256, 1, br, 0, 4);
        FORK(st, sw);   // cols ready for sw's GEMM half
        // adaptive GEMM: rows 0..127 on st, rows 128..255 on sw (bitwise-identical blocks)
        GEMMTB(st, AWH(br), AWL(br), COLSH(br), COLSL(br), gdef,
               128, HW2, 2304, 256LL * 2304, 2304LL * HW2, 256LL * HW2, 0);
        GEMMTB(sw, AWH(br) + 128LL * 2304, AWL(br) + 128LL * 2304, COLSH(br), COLSL(br),
               gdef + 128LL * HW2, 128, HW2, 2304,
               256LL * 2304, 2304LL * HW2, 256LL * HW2, 0);
        // full cross-stream barrier: BOTH GEMM halves (readers of COLSH) must drain
        // before either stream overwrites COLSH below.
        FORK(st, sw);
        FORK(sw, st);
        // s_net dim2col halves (now safe to overwrite cols)
        DIM2COL(st, gdef, 256LL * HW2, nullptr, 256, 1, br, 0, 2);
        DIM2COL(sw, gdef, 256LL * HW2, nullptr, 256, 1, br, 2, 2);
        FORK(sw, st);   // join: full cols ready
        GEMMTB(st, s1h, s1l, COLSH(br), COLSL(br), S1O(br), 128, HW2, 2304,
               0, 2304LL * HW2, 128LL * HW2, 1);
        DIM2COL(st, S1O(br), 128LL * HW2, nullptr, 128, 0, br, 0, 2);
        GEMMA(st, s2w, COLS(br), S2O(br), 64, HW2, 1152,
              0, 1152LL * HW2, 64LL * HW2, nullptr, 1);
        conv3x3_direct<<<dim3(9, 1, 2), 256, 0, st>>>(S2O(br), 64LL * HW2, s3w, gsw,
                                                      (long long)HW2, 64, 1);
    };

    // branch 0: stsn on sM, weight on sW0; TAIL pipelined over (sM, sW0)
    STSN(sM, 0);
    WEIGHT(sW0, 0);
    FORK(sW0, sM);
    TAIL(sM, sW0, 0, def0, swa);

    // branch 1: stsn on sS1, weight on sW1; TAIL pipelined over (sS1, sW1)
    STSN(sS1, 1);
    WEIGHT(sW1, 1);
    FORK(sW1, sS1);
    TAIL(sS1, sW1, 1, def1, swb);
    FORK(sS1, sM);

    {
        int tot = 2 * 256 * HW2;
        final_k<<<(tot + 255) / 256, 256, 0, sM>>>(def0, def1, swa, swb, out, tot);
    }

    for (int i = 0; i < NEV; i++) cudaEventDestroy(ev[i]);
    cudaStreamDestroy(sW0);
    cudaStreamDestroy(sS1);
    cudaStreamDestroy(sW1);
}

// round 13
// speedup vs baseline: 1.0165x; 1.0083x over previous
#include <cuda_runtime.h>
#include <cuda_bf16.h>
#include <math.h>

#define HW2 2304
#define HH 48
#define WW 48

typedef unsigned int u32;
typedef unsigned short u16;

// ---------------- device scratch (no allocations allowed; [2] = per-branch) ----------------
__device__ float g_xenc  [2*64 *HW2];
__device__ float g_yenc  [2*64 *HW2];
__device__ float g_f512a [2][2*512*HW2];
__device__ float g_f512b [2][2*512*HW2];
__device__ float g_cols  [2][2*1600*HW2];
__device__ u16   g_colsh [2][2*4608*HW2];
__device__ u16   g_colsl [2][2*4608*HW2];
__device__ u16   g_awh   [2][2*256*2304];
__device__ u16   g_awl   [2][2*256*2304];
__device__ u16   g_dwh   [3*512*4608];
__device__ u16   g_dwl   [3*512*4608];
__device__ u16   g_d0fh  [512*2304];     // folded def_w0 (y,y) hi
__device__ u16   g_d0fl  [512*2304];     // folded def_w0 lo
__device__ float g_o0f   [18*256*9];     // folded off_w0 (y,y)
__device__ u16   g_s1h   [128*2304];
__device__ u16   g_s1l   [128*2304];
__device__ float g_offb  [2][2*18 *HW2];
__device__ float g_cpart [2][16*2*18*HW2];
__device__ float g_f177  [2][2*177*HW2];
__device__ float g_f177b [2][2*177*HW2];
__device__ float g_wb1   [2][2*64*576];
__device__ float g_wb2   [2][2*64*144];
__device__ float g_wb3   [2][2*256*36];
__device__ float g_fwb   [2][2*256];
__device__ float g_adw   [2][2*256*HW2];
__device__ float g_def0  [2*256*HW2];
__device__ float g_def1  [2*256*HW2];
__device__ float g_s1o   [2][2*128*HW2];
__device__ float g_s2o   [2][2*64*HW2];
__device__ float g_swa   [2*HW2];
__device__ float g_swb   [2*HW2];

// ---------------- helpers ----------------
__device__ __forceinline__ void split16(float x, u16& h, u16& l)
{
    __nv_bfloat16 xh = __float2bfloat16(x);
    h = __bfloat16_as_ushort(xh);
    l = __bfloat16_as_ushort(__float2bfloat16(x - __bfloat162float(xh)));
}

__global__ void convw_k(const float* __restrict__ src, u16* __restrict__ h,
                        u16* __restrict__ l, int n)
{
    int i = blockIdx.x * 256 + threadIdx.x;
    if (i >= n) return;
    u16 hh, ll;
    split16(src[i], hh, ll);
    h[i] = hh; l[i] = ll;
}

// fold conv weights over duplicated input halves: out[o][c][q] = w[o][c][q]+w[o][c+IC][q]
__global__ void foldw_k(const float* __restrict__ w, u16* __restrict__ h,
                        u16* __restrict__ l, int OC, int IC)
{
    int i = blockIdx.x * 256 + threadIdx.x;
    int n = OC * IC * 9;
    if (i >= n) return;
    int o = i / (IC * 9), r = i % (IC * 9);
    int c = r / 9, q = r % 9;
    float v = w[((long long)o * 2 * IC + c) * 9 + q]
            + w[((long long)o * 2 * IC + c + IC) * 9 + q];
    u16 hh, ll;
    split16(v, hh, ll);
    h[i] = hh; l[i] = ll;
}

__global__ void foldf_k(const float* __restrict__ w, float* __restrict__ out,
                        int OC, int IC)
{
    int i = blockIdx.x * 256 + threadIdx.x;
    int n = OC * IC * 9;
    if (i >= n) return;
    int o = i / (IC * 9), r = i % (IC * 9);
    int c = r / 9, q = r % 9;
    out[i] = w[((long long)o * 2 * IC + c) * 9 + q]
           + w[((long long)o * 2 * IC + c + IC) * 9 + q];
}

#define MMA16816(c, a, b0v, b1v) \
    asm volatile("mma.sync.aligned.m16n8k16.row.col.f32.bf16.bf16.f32 " \
        "{%0,%1,%2,%3},{%4,%5,%6,%7},{%8,%9},{%0,%1,%2,%3};" \
        : "+f"((c)[0]), "+f"((c)[1]), "+f"((c)[2]), "+f"((c)[3]) \
        : "r"((a)[0]), "r"((a)[1]), "r"((a)[2]), "r"((a)[3]), \
          "r"(b0v), "r"(b1v))

// ---------------- bf16x3 split tensor-core GEMM, pre-split inputs (R8 order) ----------------
__global__ __launch_bounds__(256)
void gemm_bf3b(const u16* __restrict__ Ah, const u16* __restrict__ Al,
               const u16* __restrict__ Bh, const u16* __restrict__ Bl,
               float* __restrict__ C, int M, int N, int K,
               long long sA, long long sB, long long sC, int relu)
{
    Ah += (long long)blockIdx.z * sA;
    Al += (long long)blockIdx.z * sA;
    Bh += (long long)blockIdx.z * sB;
    Bl += (long long)blockIdx.z * sB;
    C  += (long long)blockIdx.z * sC;

    __shared__ u32 sAh[2][128][13];
    __shared__ u32 sAl[2][128][13];
    __shared__ u32 sBh[2][64][13];
    __shared__ u32 sBl[2][64][13];

    const int tid = threadIdx.x;
    const int lane = tid & 31, warp = tid >> 5;
    const int wm = warp >> 1, wn = warp & 1;
    const int m0 = blockIdx.y * 128, n0 = blockIdx.x * 64;

    const int arow = tid >> 1, ahalf = tid & 1;
    const u16* ApH = Ah + (long long)(m0 + arow) * K + ahalf * 8;
    const u16* ApL = Al + (long long)(m0 + arow) * K + ahalf * 8;

    const int bw = warp;
    const int bn = lane * 2;
    const u16* BpH = Bh + n0 + bn;
    const u16* BpL = Bl + n0 + bn;

    float acc[2][4][4];
#pragma unroll
    for (int mt = 0; mt < 2; mt++)
#pragma unroll
        for (int nt = 0; nt < 4; nt++)
#pragma unroll
            for (int i = 0; i < 4; i++) acc[mt][nt][i] = 0.f;

    uint4 lah, lal;
    u32 lbh0, lbh1, lbl0, lbl1;

    lah = *(const uint4*)ApH;
    lal = *(const uint4*)ApL;
    lbh0 = *(const u32*)(BpH + (long long)(2 * bw) * N);
    lbh1 = *(const u32*)(BpH + (long long)(2 * bw + 1) * N);
    lbl0 = *(const u32*)(BpL + (long long)(2 * bw) * N);
    lbl1 = *(const u32*)(BpL + (long long)(2 * bw + 1) * N);
    {
        sAh[0][arow][ahalf*4+0] = lah.x; sAh[0][arow][ahalf*4+1] = lah.y;
        sAh[0][arow][ahalf*4+2] = lah.z; sAh[0][arow][ahalf*4+3] = lah.w;
        sAl[0][arow][ahalf*4+0] = lal.x; sAl[0][arow][ahalf*4+1] = lal.y;
        sAl[0][arow][ahalf*4+2] = lal.z; sAl[0][arow][ahalf*4+3] = lal.w;
        sBh[0][bn  ][bw] = __byte_perm(lbh0, lbh1, 0x5410);
        sBh[0][bn+1][bw] = __byte_perm(lbh0, lbh1, 0x7632);
        sBl[0][bn  ][bw] = __byte_perm(lbl0, lbl1, 0x5410);
        sBl[0][bn+1][bw] = __byte_perm(lbl0, lbl1, 0x7632);
    }
    __syncthreads();

    const int ar = lane >> 2, ac = lane & 3;
    int buf = 0;
    for (int k0 = 0; k0 < K; k0 += 16) {
        const bool has = (k0 + 16) < K;
        if (has) {
            lah = *(const uint4*)(ApH + k0 + 16);
            lal = *(const uint4*)(ApL + k0 + 16);
            const long long r0 = (long long)(k0 + 16 + 2 * bw) * N;
            lbh0 = *(const u32*)(BpH + r0);
            lbh1 = *(const u32*)(BpH + r0 + N);
            lbl0 = *(const u32*)(BpL + r0);
            lbl1 = *(const u32*)(BpL + r0 + N);
        }

        u32 ah[2][4], al[2][4];
#pragma unroll
        for (int mt = 0; mt < 2; mt++) {
            int r = wm * 32 + mt * 16 + ar;
            ah[mt][0] = sAh[buf][r][ac];         al[mt][0] = sAl[buf][r][ac];
            ah[mt][1] = sAh[buf][r + 8][ac];     al[mt][1] = sAl[buf][r + 8][ac];
            ah[mt][2] = sAh[buf][r][ac + 4];     al[mt][2] = sAl[buf][r][ac + 4];
            ah[mt][3] = sAh[buf][r + 8][ac + 4]; al[mt][3] = sAl[buf][r + 8][ac + 4];
        }
#pragma unroll
        for (int nt = 0; nt < 4; nt++) {
            int nr = wn * 32 + nt * 8 + ar;
            u32 bh0 = sBh[buf][nr][ac], bh1 = sBh[buf][nr][ac + 4];
            u32 bl0 = sBl[buf][nr][ac], bl1 = sBl[buf][nr][ac + 4];
#pragma unroll
            for (int mt = 0; mt < 2; mt++) {
                MMA16816(acc[mt][nt], ah[mt], bh0, bh1);
                MMA16816(acc[mt][nt], ah[mt], bl0, bl1);
                MMA16816(acc[mt][nt], al[mt], bh0, bh1);
            }
        }

        if (has) {
            int nb = buf ^ 1;
            sAh[nb][arow][ahalf*4+0] = lah.x; sAh[nb][arow][ahalf*4+1] = lah.y;
            sAh[nb][arow][ahalf*4+2] = lah.z; sAh[nb][arow][ahalf*4+3] = lah.w;
            sAl[nb][arow][ahalf*4+0] = lal.x; sAl[nb][arow][ahalf*4+1] = lal.y;
            sAl[nb][arow][ahalf*4+2] = lal.z; sAl[nb][arow][ahalf*4+3] = lal.w;
            sBh[nb][bn  ][bw] = __byte_perm(lbh0, lbh1, 0x5410);
            sBh[nb][bn+1][bw] = __byte_perm(lbh0, lbh1, 0x7632);
            sBl[nb][bn  ][bw] = __byte_perm(lbl0, lbl1, 0x5410);
            sBl[nb][bn+1][bw] = __byte_perm(lbl0, lbl1, 0x7632);
        }
        __syncthreads();
        buf ^= 1;
    }

#pragma unroll
    for (int mt = 0; mt < 2; mt++) {
        int r = m0 + wm * 32 + mt * 16 + ar;
#pragma unroll
        for (int nt = 0; nt < 4; nt++) {
            int c = n0 + wn * 32 + nt * 8 + ac * 2;
            float2 v0 = make_float2(acc[mt][nt][0], acc[mt][nt][1]);
            float2 v1 = make_float2(acc[mt][nt][2], acc[mt][nt][3]);
            if (relu) {
                v0.x = fmaxf(v0.x, 0.f); v0.y = fmaxf(v0.y, 0.f);
                v1.x = fmaxf(v1.x, 0.f); v1.y = fmaxf(v1.y, 0.f);
            }
            *(float2*)&C[(long long)r * N + c] = v0;
            *(float2*)&C[(long long)(r + 8) * N + c] = v1;
        }
    }
}

// ---------------- aligned fast fp32 GEMM ----------------
template<int RN>
__global__ __launch_bounds__(256)
void gemm_al(const float* __restrict__ A, const float* __restrict__ B,
             float* __restrict__ C, int M, int N, int K,
             long long sA, long long sB, long long sC,
             const float* __restrict__ bias, int relu)
{
    constexpr int TN = 16 * RN;
    A += (long long)blockIdx.z * sA;
    B += (long long)blockIdx.z * sB;
    C += (long long)blockIdx.z * sC;

    __shared__ float As[2][16][68];
    __shared__ float Bs[2][16][TN];

    const int tid = threadIdx.x;
    const int tx = tid & 15, ty = tid >> 4;
    const int m0 = blockIdx.y * 64, n0 = blockIdx.x * TN;

    const int ar = tid >> 2;
    const int ak = (tid & 3) * 4;
    const int bk = tid >> 4;
    const int bn = (tid & 15) * RN;

    const float* Ap = A + (long long)(m0 + ar) * K + ak;
    const float* Bp = B + (long long)bk * N + n0 + bn;

    float acc[4][RN];
#pragma unroll
    for (int i = 0; i < 4; i++)
#pragma unroll
        for (int j = 0; j < RN; j++) acc[i][j] = 0.f;

    {
        float4 av = *(const float4*)Ap;
        As[0][ak + 0][ar] = av.x; As[0][ak + 1][ar] = av.y;
        As[0][ak + 2][ar] = av.z; As[0][ak + 3][ar] = av.w;
#pragma unroll
        for (int h = 0; h < RN / 4; h++)
            *(float4*)&Bs[0][bk][bn + h * 4] = *(const float4*)(Bp + h * 4);
    }
    __syncthreads();

    int buf = 0;
    for (int k0 = 0; k0 < K; k0 += 16) {
        const bool has = (k0 + 16) < K;
        float4 la;
        float4 lbv[RN / 4];
        if (has) {
            la = *(const float4*)(Ap + k0 + 16);
#pragma unroll
            for (int h = 0; h < RN / 4; h++)
                lbv[h] = *(const float4*)(Bp + (long long)(k0 + 16) * N + h * 4);
        }

#pragma unroll
        for (int kk = 0; kk < 16; kk++) {
            float4 a4 = *(const float4*)&As[buf][kk][ty * 4];
            float a[4] = {a4.x, a4.y, a4.z, a4.w};
            float b[RN];
#pragma unroll
            for (int h = 0; h < RN / 4; h++) {
                float4 b4 = *(const float4*)&Bs[buf][kk][h * 64 + tx * 4];
                b[h * 4 + 0] = b4.x; b[h * 4 + 1] = b4.y;
                b[h * 4 + 2] = b4.z; b[h * 4 + 3] = b4.w;
            }
#pragma unroll
            for (int i = 0; i < 4; i++)
#pragma unroll
                for (int j = 0; j < RN; j++) acc[i][j] += a[i] * b[j];
        }

        if (has) {
            int nb = buf ^ 1;
            As[nb][ak + 0][ar] = la.x; As[nb][ak + 1][ar] = la.y;
            As[nb][ak + 2][ar] = la.z; As[nb][ak + 3][ar] = la.w;
#pragma unroll
            for (int h = 0; h < RN / 4; h++)
                *(float4*)&Bs[nb][bk][bn + h * 4] = lbv[h];
        }
        __syncthreads();
        buf ^= 1;
    }

#pragma unroll
    for (int i = 0; i < 4; i++) {
        int m = m0 + ty * 4 + i;
        float bv = bias ? bias[m] : 0.f;
#pragma unroll
        for (int h = 0; h < RN / 4; h++) {
            float4 v;
            v.x = acc[i][h * 4 + 0] + bv;
            v.y = acc[i][h * 4 + 1] + bv;
            v.z = acc[i][h * 4 + 2] + bv;
            v.w = acc[i][h * 4 + 3] + bv;
            if (relu) {
                v.x = fmaxf(v.x, 0.f); v.y = fmaxf(v.y, 0.f);
                v.z = fmaxf(v.z, 0.f); v.w = fmaxf(v.w, 0.f);
            }
            *(float4*)&C[(long long)m * N + n0 + h * 64 + tx * 4] = v;
        }
    }
}

// ---------------- fallback 64x64 GEMM (any shape) ----------------
__global__ void gemm64(const float* __restrict__ A, const float* __restrict__ B,
                       float* __restrict__ C, int M, int N, int K,
                       long long sA, long long sB, long long sC,
                       const float* __restrict__ bias, int relu)
{
    A += (long long)blockIdx.z * sA;
    B += (long long)blockIdx.z * sB;
    C += (long long)blockIdx.z * sC;
    __shared__ float As[16][64];
    __shared__ float Bs[16][68];
    int tx = threadIdx.x, ty = threadIdx.y;
    int tid = ty * 16 + tx;
    int m0 = blockIdx.y * 64, n0 = blockIdx.x * 64;
    int mA = tid >> 2, kA = (tid & 3) * 4;
    int kB = tid >> 4, nB = (tid & 15) * 4;
    float acc[4][4];
#pragma unroll
    for (int i = 0; i < 4; i++)
#pragma unroll
        for (int j = 0; j < 4; j++) acc[i][j] = 0.f;

    for (int k0 = 0; k0 < K; k0 += 16) {
#pragma unroll
        for (int i = 0; i < 4; i++) {
            int k = k0 + kA + i;
            As[kA + i][mA] = (m0 + mA < M && k < K) ? A[(long long)(m0 + mA) * K + k] : 0.f;
        }
#pragma unroll
        for (int i = 0; i < 4; i++) {
            int n = n0 + nB + i;
            Bs[kB][nB + i] = (k0 + kB < K && n < N) ? B[(long long)(k0 + kB) * N + n] : 0.f;
        }
        __syncthreads();
#pragma unroll
        for (int kk = 0; kk < 16; kk++) {
            float a[4], b[4];
#pragma unroll
            for (int i = 0; i < 4; i++) a[i] = As[kk][ty * 4 + i];
#pragma unroll
            for (int j = 0; j < 4; j++) b[j] = Bs[kk][tx * 4 + j];
#pragma unroll
            for (int i = 0; i < 4; i++)
#pragma unroll
                for (int j = 0; j < 4; j++) acc[i][j] += a[i] * b[j];
        }
        __syncthreads();
    }
#pragma unroll
    for (int i = 0; i < 4; i++) {
        int m = m0 + ty * 4 + i;
        if (m >= M) continue;
        float bv = bias ? bias[m] : 0.f;
#pragma unroll
        for (int j = 0; j < 4; j++) {
            int n = n0 + tx * 4 + j;
            if (n >= N) continue;
            float v = acc[i][j] + bv;
            if (relu) v = fmaxf(v, 0.f);
            C[(long long)m * N + n] = v;
        }
    }
}

// ---------------- C->18 offset-head 3x3 conv (chunks of 32 channels) ----------------
__global__ void conv18_k(const float* __restrict__ in, long long inB,
                         const float* __restrict__ w, float* __restrict__ part, int C)
{
    const int t = blockIdx.x, cc = blockIdx.y, b = blockIdx.z;
    const int tid = threadIdx.x;
    const int hw = t * 256 + tid;
    const int h = hw / WW, x = hw % WW;
    const int hf = (t * 256) / WW;

    __shared__ float sIn[4][9 * WW];
    __shared__ float sW[4][18 * 9];

    float acc[18];
#pragma unroll
    for (int o = 0; o < 18; o++) acc[o] = 0.f;

    const float* ib = in + (long long)b * inB + (long long)(cc * 32) * HW2;
    const int lr = h - (hf - 1);

    for (int cs = 0; cs < 32; cs += 4) {
        for (int i = tid; i < 4 * 9 * WW; i += 256) {
            int c = i / (9 * WW), r = i % (9 * WW);
            int row = hf - 1 + r / WW, col = r % WW;
            float v = 0.f;
            if (row >= 0 && row < HH) v = ib[(long long)(cs + c) * HW2 + row * WW + col];
            sIn[c][r] = v;
        }
        for (int i = tid; i < 4 * 162; i += 256) {
            int c = i / 162, r = i % 162;
            int o = r / 9, q = r % 9;
            sW[c][r] = w[((long long)o * C + (cc * 32 + cs + c)) * 9 + q];
        }
        __syncthreads();

#pragma unroll
        for (int c = 0; c < 4; c++) {
            float tap[9];
#pragma unroll
            for (int ki = 0; ki < 3; ki++)
#pragma unroll
                for (int kj = 0; kj < 3; kj++) {
                    int xx = x - 1 + kj;
                    float v = 0.f;
                    if (xx >= 0 && xx < WW) v = sIn[c][(lr - 1 + ki) * WW + xx];
                    tap[ki * 3 + kj] = v;
                }
#pragma unroll
            for (int o = 0; o < 18; o++) {
                float s = acc[o];
#pragma unroll
                for (int q = 0; q < 9; q++) s += sW[c][o * 9 + q] * tap[q];
                acc[o] = s;
            }
        }
        __syncthreads();
    }

    float* pp = part + ((long long)cc * 2 + b) * 18 * HW2;
#pragma unroll
    for (int o = 0; o < 18; o++) pp[(long long)o * HW2 + hw] = acc[o];
}

__global__ void reduce18_k(const float* __restrict__ part, float* __restrict__ out, int nc)
{
    int idx = blockIdx.x * 256 + threadIdx.x;
    if (idx >= 2 * 18 * HW2) return;
    int b = idx / (18 * HW2);
    int r = idx % (18 * HW2);
    float s = 0.f;
    for (int c = 0; c < nc; c++) s += part[((long long)c * 2 + b) * 18 * HW2 + r];
    out[(long long)b * 18 * HW2 + r] = s;
}

// ---------------- deformable (or plain) 3x3 s1 p1 im2col (zofs = channel-chunk offset) ----------------
__global__ void deform_im2col_k(const float* __restrict__ src, long long srcB,
                                const float* __restrict__ off,
                                float* __restrict__ colsF,
                                u16* __restrict__ colsH, u16* __restrict__ colsL,
                                int C, int mode, int zofs)
{
    int hw = blockIdx.x * 256 + threadIdx.x;
    if (hw >= HW2) return;
    int bq = blockIdx.y;
    int b = bq / 9, q = bq % 9;
    int ki = q / 3, kj = q % 3;
    int h = hw / WW, w = hw % WW;
    const float* sb = src + (long long)b * srcB;
    long long cbase = (long long)b * C * 9 * HW2;
    int c0 = (blockIdx.z + zofs) * 64;
    int c1 = c0 + 64; if (c1 > C) c1 = C;

    float w00, w01, w10, w11;
    int i00, i01, i10, i11;
    if (off == nullptr) {
        int y = h - 1 + ki, x = w - 1 + kj;
        bool vin = (y >= 0 && y < HH && x >= 0 && x < WW);
        w00 = vin ? 1.f : 0.f; w01 = w10 = w11 = 0.f;
        i00 = vin ? (y * WW + x) : 0; i01 = i10 = i11 = 0;
    } else {
        float py = (float)(h - 1 + ki) + off[((long long)b * 18 + 2 * q) * HW2 + hw];
        float px = (float)(w - 1 + kj) + off[((long long)b * 18 + 2 * q + 1) * HW2 + hw];
        float fy = floorf(py), fx = floorf(px);
        float ay = py - fy, ax = px - fx;
        int y0 = (int)fy, x0 = (int)fx;
        int y1 = y0 + 1, x1 = x0 + 1;
        bool by0 = (y0 >= 0 && y0 < HH), by1 = (y1 >= 0 && y1 < HH);
        bool bx0 = (x0 >= 0 && x0 < WW), bx1 = (x1 >= 0 && x1 < WW);
        int yc0 = min(max(y0, 0), HH - 1), yc1 = min(max(y1, 0), HH - 1);
        int xc0 = min(max(x0, 0), WW - 1), xc1 = min(max(x1, 0), WW - 1);
        w00 = (by0 && bx0) ? (1.f - ay) * (1.f - ax) : 0.f;
        w01 = (by0 && bx1) ? (1.f - ay) * ax : 0.f;
        w10 = (by1 && bx0) ? ay * (1.f - ax) : 0.f;
        w11 = (by1 && bx1) ? ay * ax : 0.f;
        i00 = yc0 * WW + xc0; i01 = yc0 * WW + xc1;
        i10 = yc1 * WW + xc0; i11 = yc1 * WW + xc1;
    }

    for (int c = c0; c < c1; c++) {
        const float* s = sb + (long long)c * HW2;
        float v = w00 * s[i00] + w01 * s[i01] + w10 * s[i10] + w11 * s[i11];
        long long idx = cbase + ((long long)c * 9 + q) * HW2 + hw;
        if (mode == 0) {
            colsF[idx] = v;
        } else {
            u16 hh, ll;
            split16(v, hh, ll);
            colsH[idx] = hh; colsL[idx] = ll;
        }
    }
}

// ---------------- generic strided im2col ----------------
__global__ void im2col_g(const float* __restrict__ src, long long srcB,
                         float* __restrict__ cols,
                         int C, int H, int W, int KH, int KW,
                         int stride, int pad, int OH, int OW)
{
    int ohw = blockIdx.x * 256 + threadIdx.x;
    int OHW = OH * OW;
    if (ohw >= OHW) return;
    int row = blockIdx.y;
    int b = blockIdx.z;
    int kk = row % (KH * KW);
    int c = row / (KH * KW);
    int kh = kk / KW, kw = kk % KW;
    int oh = ohw / OW, ow = ohw % OW;
    int ih = oh * stride - pad + kh;
    int iw = ow * stride - pad + kw;
    float v = 0.f;
    if (ih >= 0 && ih < H && iw >= 0 && iw < W)
        v = src[(long long)b * srcB + ((long long)c * H + ih) * W + iw];
    cols[((long long)b * C * KH * KW + row) * OHW + ohw] = v;
}

// ---------------- direct 3x3 conv (tiny s3: 64->1) ----------------
__global__ void conv3x3_direct(const float* __restrict__ in, long long inB,
                               const float* __restrict__ w, float* __restrict__ out,
                               long long outB, int C, int relu)
{
    int hw = blockIdx.x * 256 + threadIdx.x;
    if (hw >= HW2) return;
    int o = blockIdx.y, b = blockIdx.z;
    int h = hw / WW, x = hw % WW;
    const float* ib = in + (long long)b * inB;
    const float* wo = w + (long long)o * C * 9;
    float acc = 0.f;
    for (int c = 0; c < C; c++) {
        const float* ic = ib + (long long)c * HW2;
        const float* wc = wo + c * 9;
#pragma unroll
        for (int kh = 0; kh < 3; kh++) {
            int ih = h + kh - 1;
            if (ih < 0 || ih >= HH) continue;
#pragma unroll
            for (int kw = 0; kw < 3; kw++) {
                int iw = x + kw - 1;
                if (iw < 0 || iw >= WW) continue;
                acc += ic[ih * WW + iw] * wc[kh * 3 + kw];
            }
        }
    }
    if (relu) acc = fmaxf(acc, 0.f);
    out[(long long)b * outB + (long long)o * HW2 + hw] = acc;
}

// ---------------- elementwise kernels ----------------
__global__ void concat_k(const float* __restrict__ a, const float* __restrict__ b_,
                         float* __restrict__ o, long long imgStride)
{
    int idx = blockIdx.x * 256 + threadIdx.x;
    if (idx >= 2 * 512 * HW2) return;
    int bb = idx / (512 * HW2);
    int c = (idx / HW2) % 512;
    int hw = idx % HW2;
    float v = (c < 256) ? a[bb * imgStride + (long long)c * HW2 + hw]
                        : b_[bb * imgStride + (long long)(c - 256) * HW2 + hw];
    o[idx] = v;
}

__global__ void corr_k(const float* __restrict__ Ra, const float* __restrict__ Tb,
                       float* __restrict__ f177)
{
    int idx = blockIdx.x * 256 + threadIdx.x;
    if (idx >= 2 * 49 * HW2) return;
    int b = idx / (49 * HW2);
    int q = (idx / HW2) % 49;
    int hw = idx % HW2;
    int h = hw / WW, w = hw % WW;
    int dy = 2 * ((q / 7) - 3), dx = 2 * ((q % 7) - 3);
    int hh = h + dy, ww = w + dx;
    float s = 0.f;
    if (hh >= 0 && hh < HH && ww >= 0 && ww < WW) {
        const float* a = Ra + (long long)b * (2 * 64 * HW2) + hw;
        const float* bp = Tb + (long long)b * (2 * 64 * HW2) + hh * WW + ww;
        for (int c = 0; c < 64; c++) s += a[c * HW2] * bp[c * HW2];
    }
    f177[((long long)b * 177 + q) * HW2 + hw] = s * (1.f / 64.f);
}

__global__ void pack_k(const float* __restrict__ eA, const float* __restrict__ eB,
                       float* __restrict__ f177)
{
    int idx = blockIdx.x * 256 + threadIdx.x;
    if (idx >= 2 * 64 * HW2) return;
    int b = idx / (64 * HW2);
    int c = (idx / HW2) % 64;
    int hw = idx % HW2;
    f177[((long long)b * 177 + 49 + c) * HW2 + hw] = eA[idx];
    f177[((long long)b * 177 + 113 + c) * HW2 + hw] = eB[idx];
}

__global__ void mean36_k(const float* __restrict__ in, float* __restrict__ fw, int total)
{
    int i = blockIdx.x * 256 + threadIdx.x;
    if (i >= total) return;
    float s = 0.f;
#pragma unroll
    for (int j = 0; j < 36; j++) s += in[i * 36 + j];
    fw[i] = s * (1.f / 36.f);
}

__global__ void mkw_k(const float* __restrict__ fw, const float* __restrict__ Wt,
                      const float* __restrict__ Bi, float* __restrict__ adw,
                      int M, int Kc, int total)
{
    int idx = blockIdx.x * 256 + threadIdx.x;
    if (idx >= total) return;
    int b = idx / (M * Kc);
    int r = idx - b * M * Kc;
    int o = r / Kc;
    adw[idx] = fw[b * M + o] * Wt[r] + Bi[r];
}

__global__ void final_k(const float* __restrict__ d0, const float* __restrict__ d1,
                        const float* __restrict__ s0p, const float* __restrict__ s1p,
                        float* __restrict__ out, int total)
{
    int idx = blockIdx.x * 256 + threadIdx.x;
    if (idx >= total) return;
    int b = idx / (256 * HW2);
    int hw = idx % HW2;
    float s0 = s0p[b * HW2 + hw];
    float s1 = s1p[b * HW2 + hw];
    const float eps = 1e-8f;
    float wx = (s0 * s1) / (fmaxf(fabsf(s0), eps) * fmaxf(fabsf(s1), eps));
    float wy = (s1 * s1) / (fmaxf(fabsf(s1), eps) * fmaxf(fabsf(s1), eps));
    float mx = fmaxf(wx, wy);
    float e0 = expf(wx - mx), e1 = expf(wy - mx);
    float inv = 1.f / (e0 + e1);
    out[idx] = d0[idx] * (e0 * inv) + d1[idx] * (e1 * inv);
}

// ---------------- host orchestration (4-lane overlap, y-fold for branch 1) ----------------
extern "C" void kernel_launch(void* const* d_in, const int* in_sizes, int n_in,
                              void* d_out, int out_size)
{
    (void)in_sizes; (void)n_in; (void)out_size;
    const float* R0     = (const float*)d_in[0];
    const float* T0     = (const float*)d_in[1];
    const float* inp    = (const float*)d_in[2];
    const float* enc0_w = (const float*)d_in[3];
    const float* enc0_b = (const float*)d_in[4];
    const float* enc1_w = (const float*)d_in[5];
    const float* enc1_b = (const float*)d_in[6];
    const float* offw[4] = {(const float*)d_in[7], (const float*)d_in[8],
                            (const float*)d_in[9], (const float*)d_in[10]};
    const float* defw[3] = {(const float*)d_in[11], (const float*)d_in[12],
                            (const float*)d_in[13]};
    const float* w0a = (const float*)d_in[14];
    const float* w0b = (const float*)d_in[15];
    const float* w0c = (const float*)d_in[16];
    const float* w1a = (const float*)d_in[17];
    const float* w1b = (const float*)d_in[18];
    const float* w1c = (const float*)d_in[19];
    const float* wx_w  = (const float*)d_in[20];
    const float* wx_b  = (const float*)d_in[21];
    const float* wxf_w = (const float*)d_in[22];
    const float* wxf_b = (const float*)d_in[23];
    const float* s1w = (const float*)d_in[24];
    const float* s2w = (const float*)d_in[25];
    const float* s3w = (const float*)d_in[26];
    float* out = (float*)d_out;

    float *xenc, *yenc, *def0, *def1, *swa, *swb;
    float *f512aP, *f512bP, *colsP, *offP, *cpartP, *f177P, *f177bP;
    float *wb1P, *wb2P, *wb3P, *fwP, *adwP, *s1oP, *s2oP, *o0f;
    u16 *colshP, *colslP, *awhP, *awlP, *dwh, *dwl, *s1h, *s1l, *d0fh, *d0fl;
    cudaGetSymbolAddress((void**)&xenc,   g_xenc);
    cudaGetSymbolAddress((void**)&yenc,   g_yenc);
    cudaGetSymbolAddress((void**)&f512aP, g_f512a);
    cudaGetSymbolAddress((void**)&f512bP, g_f512b);
    cudaGetSymbolAddress((void**)&colsP,  g_cols);
    cudaGetSymbolAddress((void**)&colshP, g_colsh);
    cudaGetSymbolAddress((void**)&colslP, g_colsl);
    cudaGetSymbolAddress((void**)&awhP,   g_awh);
    cudaGetSymbolAddress((void**)&awlP,   g_awl);
    cudaGetSymbolAddress((void**)&dwh,    g_dwh);
    cudaGetSymbolAddress((void**)&dwl,    g_dwl);
    cudaGetSymbolAddress((void**)&d0fh,   g_d0fh);
    cudaGetSymbolAddress((void**)&d0fl,   g_d0fl);
    cudaGetSymbolAddress((void**)&o0f,    g_o0f);
    cudaGetSymbolAddress((void**)&s1h,    g_s1h);
    cudaGetSymbolAddress((void**)&s1l,    g_s1l);
    cudaGetSymbolAddress((void**)&offP,   g_offb);
    cudaGetSymbolAddress((void**)&cpartP, g_cpart);
    cudaGetSymbolAddress((void**)&f177P,  g_f177);
    cudaGetSymbolAddress((void**)&f177bP, g_f177b);
    cudaGetSymbolAddress((void**)&wb1P,   g_wb1);
    cudaGetSymbolAddress((void**)&wb2P,   g_wb2);
    cudaGetSymbolAddress((void**)&wb3P,   g_wb3);
    cudaGetSymbolAddress((void**)&fwP,    g_fwb);
    cudaGetSymbolAddress((void**)&adwP,   g_adw);
    cudaGetSymbolAddress((void**)&def0,   g_def0);
    cudaGetSymbolAddress((void**)&def1,   g_def1);
    cudaGetSymbolAddress((void**)&s1oP,   g_s1o);
    cudaGetSymbolAddress((void**)&s2oP,   g_s2o);
    cudaGetSymbolAddress((void**)&swa,    g_swa);
    cudaGetSymbolAddress((void**)&swb,    g_swb);

    auto F512A = [&](int br){ return f512aP + (long long)br * (2*512*HW2); };
    auto F512B = [&](int br){ return f512bP + (long long)br * (2*512*HW2); };
    auto COLS  = [&](int br){ return colsP  + (long long)br * (2*1600*HW2); };
    auto COLSH = [&](int br){ return colshP + (long long)br * (2LL*4608*HW2); };
    auto COLSL = [&](int br){ return colslP + (long long)br * (2LL*4608*HW2); };
    auto AWH   = [&](int br){ return awhP   + (long long)br * (2*256*2304); };
    auto AWL   = [&](int br){ return awlP   + (long long)br * (2*256*2304); };
    auto OFF   = [&](int br){ return offP   + (long long)br * (2*18*HW2); };
    auto CPART = [&](int br){ return cpartP + (long long)br * (16LL*2*18*HW2); };
    auto F177  = [&](int br){ return f177P  + (long long)br * (2*177*HW2); };
    auto F177B = [&](int br){ return f177bP + (long long)br * (2*177*HW2); };
    auto WB1   = [&](int br){ return wb1P + (long long)br * (2*64*576); };
    auto WB2   = [&](int br){ return wb2P + (long long)br * (2*64*144); };
    auto WB3   = [&](int br){ return wb3P + (long long)br * (2*256*36); };
    auto FW    = [&](int br){ return fwP  + (long long)br * (2*256); };
    auto ADW   = [&](int br){ return adwP + (long long)br * (2*256*HW2); };
    auto S1O   = [&](int br){ return s1oP + (long long)br * (2*128*HW2); };
    auto S2O   = [&](int br){ return s2oP + (long long)br * (2*64*HW2); };

    const long long imgStride = 2LL * 256 * HW2;
    const int DW = 512 * 4608;

    cudaStream_t sM = 0, sW0, sS1, sW1;
    cudaStreamCreateWithFlags(&sW0, cudaStreamNonBlocking);
    cudaStreamCreateWithFlags(&sS1, cudaStreamNonBlocking);
    cudaStreamCreateWithFlags(&sW1, cudaStreamNonBlocking);
    const int NEV = 8;
    cudaEvent_t ev[NEV];
    for (int i = 0; i < NEV; i++) cudaEventCreateWithFlags(&ev[i], cudaEventDisableTiming);
    int evi = 0;
    auto FORK = [&](cudaStream_t from, cudaStream_t to) {
        cudaEventRecord(ev[evi], from);
        cudaStreamWaitEvent(to, ev[evi], 0);
        evi++;
    };

    auto GEMMTB = [&](cudaStream_t st, const u16* Ah, const u16* Al,
                      const u16* Bh, const u16* Bl, float* C,
                      int M, int N, int K,
                      long long sA, long long sB, long long sC, int relu) {
        gemm_bf3b<<<dim3(N / 64, M / 128, 2), 256, 0, st>>>(Ah, Al, Bh, Bl,
                                                            C, M, N, K, sA, sB, sC, relu);
    };
    auto GEMMA = [&](cudaStream_t st, const float* A, const float* Bm, float* C,
                     int M, int N, int K, long long sA, long long sB, long long sC,
                     const float* bias, int relu) {
        gemm_al<4><<<dim3(N / 64, M / 64, 2), 256, 0, st>>>(A, Bm, C, M, N, K,
                                                            sA, sB, sC, bias, relu);
    };
    auto GEMMF = [&](cudaStream_t st, const float* A, const float* Bm, float* C,
                     int M, int N, int K, long long sA, long long sB, long long sC,
                     const float* bias, int relu) {
        dim3 g((N + 63) / 64, (M + 63) / 64, 2);
        gemm64<<<g, dim3(16, 16), 0, st>>>(A, Bm, C, M, N, K, sA, sB, sC, bias, relu);
    };
    auto DIM2COL = [&](cudaStream_t st, const float* src, long long sB,
                       const float* offp, int C, int mode, int br, int zofs, int zcnt) {
        dim3 g((HW2 + 255) / 256, 18, zcnt);
        deform_im2col_k<<<g, 256, 0, st>>>(src, sB, offp, COLS(br),
                                           COLSH(br), COLSL(br), C, mode, zofs);
    };
    auto IM2COL = [&](cudaStream_t st, const float* src, long long sB, int C,
                      int H, int W, int KH, int KW, int stp, int pad,
                      int OH, int OW, int br) {
        dim3 g((OH * OW + 255) / 256, C * KH * KW, 2);
        im2col_g<<<g, 256, 0, st>>>(src, sB, COLS(br), C, H, W, KH, KW, stp, pad, OH, OW);
    };
    auto WBRANCH = [&](cudaStream_t st, const float* feat, const float* wa,
                       const float* wb, const float* wc, int Mc, int br) {
        IM2COL(st, feat, 177LL * HW2, 177, 48, 48, 5, 5, 2, 2, 24, 24, br);
        GEMMF(st, wa, COLS(br), WB1(br), 64, 576, 4425, 0, 4425LL * 576, 64LL * 576,
              nullptr, 1);
        IM2COL(st, WB1(br), 64LL * 576, 64, 24, 24, 5, 5, 2, 2, 12, 12, br);
        GEMMF(st, wb, COLS(br), WB2(br), 64, 144, 1600, 0, 1600LL * 144, 64LL * 144,
              nullptr, 1);
        IM2COL(st, WB2(br), 64LL * 144, 64, 12, 12, 3, 3, 2, 1, 6, 6, br);
        GEMMF(st, wc, COLS(br), WB3(br), Mc, 36, 576, 0, 576LL * 36,
              (long long)Mc * 36, nullptr, 0);
        int tot = 2 * Mc;
        mean36_k<<<(tot + 255) / 256, 256, 0, st>>>(WB3(br), FW(br), tot);
    };

    // ---- init: hoisted weight splits + folds + encoders ----
    for (int i = 0; i < 3; i++)
        convw_k<<<(DW + 255) / 256, 256, 0, sM>>>(defw[i], dwh + (long long)i * DW,
                                                  dwl + (long long)i * DW, DW);
    convw_k<<<(128 * 2304 + 255) / 256, 256, 0, sM>>>(s1w, s1h, s1l, 128 * 2304);
    foldw_k<<<(512 * 2304 + 255) / 256, 256, 0, sM>>>(defw[0], d0fh, d0fl, 512, 256);
    foldf_k<<<(18 * 256 * 9 + 255) / 256, 256, 0, sM>>>(offw[0], o0f, 18, 256);
    GEMMA(sM, enc0_w, inp,             xenc, 64, HW2, 256, 0, imgStride, 64LL * HW2, enc0_b, 0);
    GEMMA(sM, enc1_w, inp + 256 * HW2, yenc, 64, HW2, 256, 0, imgStride, 64LL * HW2, enc1_b, 0);
    {
        cudaEventRecord(ev[evi], sM);
        cudaStreamWaitEvent(sW0, ev[evi], 0);
        cudaStreamWaitEvent(sS1, ev[evi], 0);
        cudaStreamWaitEvent(sW1, ev[evi], 0);
        evi++;
    }

    // STSN; branch 1 iter-0 uses the (y,y) fold: C=256, K=2304, no concat
    auto STSN = [&](cudaStream_t st, int br) {
        const float* imgA = (br == 0) ? inp : inp + 256 * HW2;
        const float* imgB = inp + 256 * HW2;
        float* cur; float* oth;
        if (br == 0) {
            int tot = 2 * 512 * HW2;
            concat_k<<<(tot + 255) / 256, 256, 0, st>>>(imgA, imgB, F512A(br), imgStride);
            cur = F512A(br); oth = F512B(br);
            conv18_k<<<dim3(9, 16, 2), 256, 0, st>>>(cur, 512LL * HW2, offw[0],
                                                     CPART(br), 512);
            reduce18_k<<<(2 * 18 * HW2 + 255) / 256, 256, 0, st>>>(CPART(br), OFF(br), 16);
            DIM2COL(st, cur, 512LL * HW2, OFF(br), 512, 1, br, 0, 8);
            GEMMTB(st, dwh, dwl, COLSH(br), COLSL(br), oth, 512, HW2, 4608,
                   0, 4608LL * HW2, 512LL * HW2, 0);
        } else {
            // folded iter 0 directly on y
            conv18_k<<<dim3(9, 8, 2), 256, 0, st>>>(imgB, imgStride, o0f,
                                                    CPART(br), 256);
            reduce18_k<<<(2 * 18 * HW2 + 255) / 256, 256, 0, st>>>(CPART(br), OFF(br), 8);
            DIM2COL(st, imgB, imgStride, OFF(br), 256, 1, br, 0, 4);
            GEMMTB(st, d0fh, d0fl, COLSH(br), COLSL(br), F512B(br), 512, HW2, 2304,
                   0, 2304LL * HW2, 512LL * HW2, 0);
            oth = F512B(br);
        }
        cur = oth; oth = (cur == F512A(br)) ? F512B(br) : F512A(br);
        for (int i = 1; i < 3; i++) {
            conv18_k<<<dim3(9, 16, 2), 256, 0, st>>>(cur, 512LL * HW2, offw[i],
                                                     CPART(br), 512);
            reduce18_k<<<(2 * 18 * HW2 + 255) / 256, 256, 0, st>>>(CPART(br), OFF(br), 16);
            DIM2COL(st, cur, 512LL * HW2, OFF(br), 512, 1, br, 0, 8);
            GEMMTB(st, dwh + (long long)i * DW, dwl + (long long)i * DW,
                   COLSH(br), COLSL(br), oth, 512, HW2, 4608,
                   0, 4608LL * HW2, 512LL * HW2, 0);
            float* t = cur; cur = oth; oth = t;
        }
        conv18_k<<<dim3(9, 16, 2), 256, 0, st>>>(cur, 512LL * HW2, offw[3],
                                                 CPART(br), 512);
        reduce18_k<<<(2 * 18 * HW2 + 255) / 256, 256, 0, st>>>(CPART(br), OFF(br), 16);
    };

    auto WEIGHT = [&](cudaStream_t st, int br) {
        const float* Ra = R0 + (br == 0 ? 0 : 64 * HW2);
        const float* Tb = T0 + 64 * HW2;
        const float* eA = (br == 0) ? xenc : yenc;
        const float* eB = yenc;
        int tot = 2 * 49 * HW2;
        corr_k<<<(tot + 255) / 256, 256, 0, st>>>(Ra, Tb, F177(br));
        tot = 2 * 64 * HW2;
        pack_k<<<(tot + 255) / 256, 256, 0, st>>>(eA, eB, F177(br));
        WBRANCH(st, F177(br), w0a, w0b, w0c, 177, br);
        tot = 2 * 177 * 1593;
        mkw_k<<<(tot + 255) / 256, 256, 0, st>>>(FW(br), wx_w, wx_b, ADW(br), 177, 1593, tot);
        DIM2COL(st, F177(br), 177LL * HW2, nullptr, 177, 0, br, 0, 3);
        GEMMF(st, ADW(br), COLS(br), F177B(br), 177, HW2, 1593,
              177LL * 1593, 1593LL * HW2, 177LL * HW2, nullptr, 1);
        WBRANCH(st, F177B(br), w1a, w1b, w1c, 256, br);
        tot = 2 * 256 * 2304;
        mkw_k<<<(tot + 255) / 256, 256, 0, st>>>(FW(br), wxf_w, wxf_b, ADW(br), 256, 2304, tot);
        convw_k<<<(2 * 256 * 2304 + 255) / 256, 256, 0, st>>>(ADW(br), AWH(br), AWL(br),
                                                              2 * 256 * 2304);
    };

    // TAIL: serial (R8 schedule — pipelined variants measured neutral)
    auto TAIL = [&](cudaStream_t st, int br, float* gdef, float* gsw) {
        const float* imgA = (br == 0) ? inp : inp + 256 * HW2;
        DIM2COL(st, imgA, imgStride, OFF(br), 256, 1, br, 0, 4);
        GEMMTB(st, AWH(br), AWL(br), COLSH(br), COLSL(br), gdef, 256, HW2, 2304,
               256LL * 2304, 2304LL * HW2, 256LL * HW2, 0);
        DIM2COL(st, gdef, 256LL * HW2, nullptr, 256, 1, br, 0, 4);
        GEMMTB(st, s1h, s1l, COLSH(br), COLSL(br), S1O(br), 128, HW2, 2304,
               0, 2304LL * HW2, 128LL * HW2, 1);
        DIM2COL(st, S1O(br), 128LL * HW2, nullptr, 128, 0, br, 0, 2);
        GEMMA(st, s2w, COLS(br), S2O(br), 64, HW2, 1152,
              0, 1152LL * HW2, 64LL * HW2, nullptr, 1);
        conv3x3_direct<<<dim3(9, 1, 2), 256, 0, st>>>(S2O(br), 64LL * HW2, s3w, gsw,
                                                      (long long)HW2, 64, 1);
    };

    // branch 0: stsn on sM, weight on sW0
    STSN(sM, 0);
    WEIGHT(sW0, 0);
    FORK(sW0, sM);
    TAIL(sM, 0, def0, swa);

    // branch 1: stsn on sS1, weight on sW1
    STSN(sS1, 1);
    WEIGHT(sW1, 1);
    FORK(sW1, sS1);
    TAIL(sS1, 1, def1, swb);
    FORK(sS1, sM);

    {
        int tot = 2 * 256 * HW2;
        final_k<<<(tot + 255) / 256, 256, 0, sM>>>(def0, def1, swa, swb, out, tot);
    }

    for (int i = 0; i < NEV; i++) cudaEventDestroy(ev[i]);
    cudaStreamDestroy(sW0);
    cudaStreamDestroy(sS1);
    cudaStreamDestroy(sW1);
}

// round 15
// speedup vs baseline: 1.0535x; 1.0364x over previous
#include <cuda_runtime.h>
#include <cuda_bf16.h>
#include <math.h>

#define HW2 2304
#define HH 48
#define WW 48

typedef unsigned int u32;
typedef unsigned short u16;

// ---------------- device scratch (no allocations allowed; [2] = per-branch) ----------------
__device__ float g_xenc  [2*64 *HW2];
__device__ float g_yenc  [2*64 *HW2];
__device__ float g_f512a [2][2*512*HW2];
__device__ float g_f512b [2][2*512*HW2];
__device__ float g_cols  [2][2*1600*HW2];
__device__ u16   g_colsh [2][2*4608*HW2];
__device__ u16   g_colsl [2][2*4608*HW2];
__device__ u16   g_awh   [2][2*256*2304];
__device__ u16   g_awl   [2][2*256*2304];
__device__ u16   g_dwh   [3*512*4608];
__device__ u16   g_dwl   [3*512*4608];
__device__ u16   g_d0fh  [512*2304];     // folded def_w0 (y,y) hi
__device__ u16   g_d0fl  [512*2304];     // folded def_w0 lo
__device__ float g_o0f   [18*256*9];     // folded off_w0 (y,y)
__device__ u16   g_s1h   [128*2304];
__device__ u16   g_s1l   [128*2304];
__device__ float g_offb  [2][2*18 *HW2];
__device__ float g_cpart [2][16*2*18*HW2];
__device__ float g_f177  [2][2*177*HW2];
__device__ float g_f177b [2][2*177*HW2];
__device__ float g_wb1   [2][2*64*576];
__device__ float g_wb2   [2][2*64*144];
__device__ float g_wb3   [2][2*256*36];
__device__ float g_fwb   [2][2*256];
__device__ float g_adw   [2][2*256*HW2];
__device__ float g_def0  [2*256*HW2];
__device__ float g_def1  [2*256*HW2];
__device__ float g_s1o   [2][2*128*HW2];
__device__ float g_s2o   [2][2*64*HW2];
__device__ float g_swa   [2*HW2];
__device__ float g_swb   [2*HW2];

// ---------------- helpers ----------------
__device__ __forceinline__ void split16(float x, u16& h, u16& l)
{
    __nv_bfloat16 xh = __float2bfloat16(x);
    h = __bfloat16_as_ushort(xh);
    l = __bfloat16_as_ushort(__float2bfloat16(x - __bfloat162float(xh)));
}

__global__ void convw_k(const float* __restrict__ src, u16* __restrict__ h,
                        u16* __restrict__ l, int n)
{
    int i = blockIdx.x * 256 + threadIdx.x;
    if (i >= n) return;
    u16 hh, ll;
    split16(src[i], hh, ll);
    h[i] = hh; l[i] = ll;
}

// fold conv weights over duplicated input halves: out[o][c][q] = w[o][c][q]+w[o][c+IC][q]
__global__ void foldw_k(const float* __restrict__ w, u16* __restrict__ h,
                        u16* __restrict__ l, int OC, int IC)
{
    int i = blockIdx.x * 256 + threadIdx.x;
    int n = OC * IC * 9;
    if (i >= n) return;
    int o = i / (IC * 9), r = i % (IC * 9);
    int c = r / 9, q = r % 9;
    float v = w[((long long)o * 2 * IC + c) * 9 + q]
            + w[((long long)o * 2 * IC + c + IC) * 9 + q];
    u16 hh, ll;
    split16(v, hh, ll);
    h[i] = hh; l[i] = ll;
}

__global__ void foldf_k(const float* __restrict__ w, float* __restrict__ out,
                        int OC, int IC)
{
    int i = blockIdx.x * 256 + threadIdx.x;
    int n = OC * IC * 9;
    if (i >= n) return;
    int o = i / (IC * 9), r = i % (IC * 9);
    int c = r / 9, q = r % 9;
    out[i] = w[((long long)o * 2 * IC + c) * 9 + q]
           + w[((long long)o * 2 * IC + c + IC) * 9 + q];
}

#define MMA16816(c, a, b0v, b1v) \
    asm volatile("mma.sync.aligned.m16n8k16.row.col.f32.bf16.bf16.f32 " \
        "{%0,%1,%2,%3},{%4,%5,%6,%7},{%8,%9},{%0,%1,%2,%3};" \
        : "+f"((c)[0]), "+f"((c)[1]), "+f"((c)[2]), "+f"((c)[3]) \
        : "r"((a)[0]), "r"((a)[1]), "r"((a)[2]), "r"((a)[3]), \
          "r"(b0v), "r"(b1v))

// ---------------- bf16x3 split tensor-core GEMM, pre-split inputs (R8 order) ----------------
__global__ __launch_bounds__(256)
void gemm_bf3b(const u16* __restrict__ Ah, const u16* __restrict__ Al,
               const u16* __restrict__ Bh, const u16* __restrict__ Bl,
               float* __restrict__ C, int M, int N, int K,
               long long sA, long long sB, long long sC, int relu)
{
    Ah += (long long)blockIdx.z * sA;
    Al += (long long)blockIdx.z * sA;
    Bh += (long long)blockIdx.z * sB;
    Bl += (long long)blockIdx.z * sB;
    C  += (long long)blockIdx.z * sC;

    __shared__ u32 sAh[2][128][13];
    __shared__ u32 sAl[2][128][13];
    __shared__ u32 sBh[2][64][13];
    __shared__ u32 sBl[2][64][13];

    const int tid = threadIdx.x;
    const int lane = tid & 31, warp = tid >> 5;
    const int wm = warp >> 1, wn = warp & 1;
    const int m0 = blockIdx.y * 128, n0 = blockIdx.x * 64;

    const int arow = tid >> 1, ahalf = tid & 1;
    const u16* ApH = Ah + (long long)(m0 + arow) * K + ahalf * 8;
    const u16* ApL = Al + (long long)(m0 + arow) * K + ahalf * 8;

    const int bw = warp;
    const int bn = lane * 2;
    const u16* BpH = Bh + n0 + bn;
    const u16* BpL = Bl + n0 + bn;

    float acc[2][4][4];
#pragma unroll
    for (int mt = 0; mt < 2; mt++)
#pragma unroll
        for (int nt = 0; nt < 4; nt++)
#pragma unroll
            for (int i = 0; i < 4; i++) acc[mt][nt][i] = 0.f;

    uint4 lah, lal;
    u32 lbh0, lbh1, lbl0, lbl1;

    lah = *(const uint4*)ApH;
    lal = *(const uint4*)ApL;
    lbh0 = *(const u32*)(BpH + (long long)(2 * bw) * N);
    lbh1 = *(const u32*)(BpH + (long long)(2 * bw + 1) * N);
    lbl0 = *(const u32*)(BpL + (long long)(2 * bw) * N);
    lbl1 = *(const u32*)(BpL + (long long)(2 * bw + 1) * N);
    {
        sAh[0][arow][ahalf*4+0] = lah.x; sAh[0][arow][ahalf*4+1] = lah.y;
        sAh[0][arow][ahalf*4+2] = lah.z; sAh[0][arow][ahalf*4+3] = lah.w;
        sAl[0][arow][ahalf*4+0] = lal.x; sAl[0][arow][ahalf*4+1] = lal.y;
        sAl[0][arow][ahalf*4+2] = lal.z; sAl[0][arow][ahalf*4+3] = lal.w;
        sBh[0][bn  ][bw] = __byte_perm(lbh0, lbh1, 0x5410);
        sBh[0][bn+1][bw] = __byte_perm(lbh0, lbh1, 0x7632);
        sBl[0][bn  ][bw] = __byte_perm(lbl0, lbl1, 0x5410);
        sBl[0][bn+1][bw] = __byte_perm(lbl0, lbl1, 0x7632);
    }
    __syncthreads();

    const int ar = lane >> 2, ac = lane & 3;
    int buf = 0;
    for (int k0 = 0; k0 < K; k0 += 16) {
        const bool has = (k0 + 16) < K;
        if (has) {
            lah = *(const uint4*)(ApH + k0 + 16);
            lal = *(const uint4*)(ApL + k0 + 16);
            const long long r0 = (long long)(k0 + 16 + 2 * bw) * N;
            lbh0 = *(const u32*)(BpH + r0);
            lbh1 = *(const u32*)(BpH + r0 + N);
            lbl0 = *(const u32*)(BpL + r0);
            lbl1 = *(const u32*)(BpL + r0 + N);
        }

        u32 ah[2][4], al[2][4];
#pragma unroll
        for (int mt = 0; mt < 2; mt++) {
            int r = wm * 32 + mt * 16 + ar;
            ah[mt][0] = sAh[buf][r][ac];         al[mt][0] = sAl[buf][r][ac];
            ah[mt][1] = sAh[buf][r + 8][ac];     al[mt][1] = sAl[buf][r + 8][ac];
            ah[mt][2] = sAh[buf][r][ac + 4];     al[mt][2] = sAl[buf][r][ac + 4];
            ah[mt][3] = sAh[buf][r + 8][ac + 4]; al[mt][3] = sAl[buf][r + 8][ac + 4];
        }
#pragma unroll
        for (int nt = 0; nt < 4; nt++) {
            int nr = wn * 32 + nt * 8 + ar;
            u32 bh0 = sBh[buf][nr][ac], bh1 = sBh[buf][nr][ac + 4];
            u32 bl0 = sBl[buf][nr][ac], bl1 = sBl[buf][nr][ac + 4];
#pragma unroll
            for (int mt = 0; mt < 2; mt++) {
                MMA16816(acc[mt][nt], ah[mt], bh0, bh1);
                MMA16816(acc[mt][nt], ah[mt], bl0, bl1);
                MMA16816(acc[mt][nt], al[mt], bh0, bh1);
            }
        }

        if (has) {
            int nb = buf ^ 1;
            sAh[nb][arow][ahalf*4+0] = lah.x; sAh[nb][arow][ahalf*4+1] = lah.y;
            sAh[nb][arow][ahalf*4+2] = lah.z; sAh[nb][arow][ahalf*4+3] = lah.w;
            sAl[nb][arow][ahalf*4+0] = lal.x; sAl[nb][arow][ahalf*4+1] = lal.y;
            sAl[nb][arow][ahalf*4+2] = lal.z; sAl[nb][arow][ahalf*4+3] = lal.w;
            sBh[nb][bn  ][bw] = __byte_perm(lbh0, lbh1, 0x5410);
            sBh[nb][bn+1][bw] = __byte_perm(lbh0, lbh1, 0x7632);
            sBl[nb][bn  ][bw] = __byte_perm(lbl0, lbl1, 0x5410);
            sBl[nb][bn+1][bw] = __byte_perm(lbl0, lbl1, 0x7632);
        }
        __syncthreads();
        buf ^= 1;
    }

#pragma unroll
    for (int mt = 0; mt < 2; mt++) {
        int r = m0 + wm * 32 + mt * 16 + ar;
#pragma unroll
        for (int nt = 0; nt < 4; nt++) {
            int c = n0 + wn * 32 + nt * 8 + ac * 2;
            float2 v0 = make_float2(acc[mt][nt][0], acc[mt][nt][1]);
            float2 v1 = make_float2(acc[mt][nt][2], acc[mt][nt][3]);
            if (relu) {
                v0.x = fmaxf(v0.x, 0.f); v0.y = fmaxf(v0.y, 0.f);
                v1.x = fmaxf(v1.x, 0.f); v1.y = fmaxf(v1.y, 0.f);
            }
            *(float2*)&C[(long long)r * N + c] = v0;
            *(float2*)&C[(long long)(r + 8) * N + c] = v1;
        }
    }
}

// ---------------- aligned fast fp32 GEMM ----------------
template<int RN>
__global__ __launch_bounds__(256)
void gemm_al(const float* __restrict__ A, const float* __restrict__ B,
             float* __restrict__ C, int M, int N, int K,
             long long sA, long long sB, long long sC,
             const float* __restrict__ bias, int relu)
{
    constexpr int TN = 16 * RN;
    A += (long long)blockIdx.z * sA;
    B += (long long)blockIdx.z * sB;
    C += (long long)blockIdx.z * sC;

    __shared__ float As[2][16][68];
    __shared__ float Bs[2][16][TN];

    const int tid = threadIdx.x;
    const int tx = tid & 15, ty = tid >> 4;
    const int m0 = blockIdx.y * 64, n0 = blockIdx.x * TN;

    const int ar = tid >> 2;
    const int ak = (tid & 3) * 4;
    const int bk = tid >> 4;
    const int bn = (tid & 15) * RN;

    const float* Ap = A + (long long)(m0 + ar) * K + ak;
    const float* Bp = B + (long long)bk * N + n0 + bn;

    float acc[4][RN];
#pragma unroll
    for (int i = 0; i < 4; i++)
#pragma unroll
        for (int j = 0; j < RN; j++) acc[i][j] = 0.f;

    {
        float4 av = *(const float4*)Ap;
        As[0][ak + 0][ar] = av.x; As[0][ak + 1][ar] = av.y;
        As[0][ak + 2][ar] = av.z; As[0][ak + 3][ar] = av.w;
#pragma unroll
        for (int h = 0; h < RN / 4; h++)
            *(float4*)&Bs[0][bk][bn + h * 4] = *(const float4*)(Bp + h * 4);
    }
    __syncthreads();

    int buf = 0;
    for (int k0 = 0; k0 < K; k0 += 16) {
        const bool has = (k0 + 16) < K;
        float4 la;
        float4 lbv[RN / 4];
        if (has) {
            la = *(const float4*)(Ap + k0 + 16);
#pragma unroll
            for (int h = 0; h < RN / 4; h++)
                lbv[h] = *(const float4*)(Bp + (long long)(k0 + 16) * N + h * 4);
        }

#pragma unroll
        for (int kk = 0; kk < 16; kk++) {
            float4 a4 = *(const float4*)&As[buf][kk][ty * 4];
            float a[4] = {a4.x, a4.y, a4.z, a4.w};
            float b[RN];
#pragma unroll
            for (int h = 0; h < RN / 4; h++) {
                float4 b4 = *(const float4*)&Bs[buf][kk][h * 64 + tx * 4];
                b[h * 4 + 0] = b4.x; b[h * 4 + 1] = b4.y;
                b[h * 4 + 2] = b4.z; b[h * 4 + 3] = b4.w;
            }
#pragma unroll
            for (int i = 0; i < 4; i++)
#pragma unroll
                for (int j = 0; j < RN; j++) acc[i][j] += a[i] * b[j];
        }

        if (has) {
            int nb = buf ^ 1;
            As[nb][ak + 0][ar] = la.x; As[nb][ak + 1][ar] = la.y;
            As[nb][ak + 2][ar] = la.z; As[nb][ak + 3][ar] = la.w;
#pragma unroll
            for (int h = 0; h < RN / 4; h++)
                *(float4*)&Bs[nb][bk][bn + h * 4] = lbv[h];
        }
        __syncthreads();
        buf ^= 1;
    }

#pragma unroll
    for (int i = 0; i < 4; i++) {
        int m = m0 + ty * 4 + i;
        float bv = bias ? bias[m] : 0.f;
#pragma unroll
        for (int h = 0; h < RN / 4; h++) {
            float4 v;
            v.x = acc[i][h * 4 + 0] + bv;
            v.y = acc[i][h * 4 + 1] + bv;
            v.z = acc[i][h * 4 + 2] + bv;
            v.w = acc[i][h * 4 + 3] + bv;
            if (relu) {
                v.x = fmaxf(v.x, 0.f); v.y = fmaxf(v.y, 0.f);
                v.z = fmaxf(v.z, 0.f); v.w = fmaxf(v.w, 0.f);
            }
            *(float4*)&C[(long long)m * N + n0 + h * 64 + tx * 4] = v;
        }
    }
}

// ---------------- fallback 64x64 GEMM (any shape) ----------------
__global__ void gemm64(const float* __restrict__ A, const float* __restrict__ B,
                       float* __restrict__ C, int M, int N, int K,
                       long long sA, long long sB, long long sC,
                       const float* __restrict__ bias, int relu)
{
    A += (long long)blockIdx.z * sA;
    B += (long long)blockIdx.z * sB;
    C += (long long)blockIdx.z * sC;
    __shared__ float As[16][64];
    __shared__ float Bs[16][68];
    int tx = threadIdx.x, ty = threadIdx.y;
    int tid = ty * 16 + tx;
    int m0 = blockIdx.y * 64, n0 = blockIdx.x * 64;
    int mA = tid >> 2, kA = (tid & 3) * 4;
    int kB = tid >> 4, nB = (tid & 15) * 4;
    float acc[4][4];
#pragma unroll
    for (int i = 0; i < 4; i++)
#pragma unroll
        for (int j = 0; j < 4; j++) acc[i][j] = 0.f;

    for (int k0 = 0; k0 < K; k0 += 16) {
#pragma unroll
        for (int i = 0; i < 4; i++) {
            int k = k0 + kA + i;
            As[kA + i][mA] = (m0 + mA < M && k < K) ? A[(long long)(m0 + mA) * K + k] : 0.f;
        }
#pragma unroll
        for (int i = 0; i < 4; i++) {
            int n = n0 + nB + i;
            Bs[kB][nB + i] = (k0 + kB < K && n < N) ? B[(long long)(k0 + kB) * N + n] : 0.f;
        }
        __syncthreads();
#pragma unroll
        for (int kk = 0; kk < 16; kk++) {
            float a[4], b[4];
#pragma unroll
            for (int i = 0; i < 4; i++) a[i] = As[kk][ty * 4 + i];
#pragma unroll
            for (int j = 0; j < 4; j++) b[j] = Bs[kk][tx * 4 + j];
#pragma unroll
            for (int i = 0; i < 4; i++)
#pragma unroll
                for (int j = 0; j < 4; j++) acc[i][j] += a[i] * b[j];
        }
        __syncthreads();
    }
#pragma unroll
    for (int i = 0; i < 4; i++) {
        int m = m0 + ty * 4 + i;
        if (m >= M) continue;
        float bv = bias ? bias[m] : 0.f;
#pragma unroll
        for (int j = 0; j < 4; j++) {
            int n = n0 + tx * 4 + j;
            if (n >= N) continue;
            float v = acc[i][j] + bv;
            if (relu) v = fmaxf(v, 0.f);
            C[(long long)m * N + n] = v;
        }
    }
}

// ---------------- C->18 offset-head 3x3 conv (chunks of 32 channels) ----------------
__global__ void conv18_k(const float* __restrict__ in, long long inB,
                         const float* __restrict__ w, float* __restrict__ part, int C)
{
    const int t = blockIdx.x, cc = blockIdx.y, b = blockIdx.z;
    const int tid = threadIdx.x;
    const int hw = t * 256 + tid;
    const int h = hw / WW, x = hw % WW;
    const int hf = (t * 256) / WW;

    __shared__ float sIn[4][9 * WW];
    __shared__ float sW[4][18 * 9];

    float acc[18];
#pragma unroll
    for (int o = 0; o < 18; o++) acc[o] = 0.f;

    const float* ib = in + (long long)b * inB + (long long)(cc * 32) * HW2;
    const int lr = h - (hf - 1);

    for (int cs = 0; cs < 32; cs += 4) {
        for (int i = tid; i < 4 * 9 * WW; i += 256) {
            int c = i / (9 * WW), r = i % (9 * WW);
            int row = hf - 1 + r / WW, col = r % WW;
            float v = 0.f;
            if (row >= 0 && row < HH) v = ib[(long long)(cs + c) * HW2 + row * WW + col];
            sIn[c][r] = v;
        }
        for (int i = tid; i < 4 * 162; i += 256) {
            int c = i / 162, r = i % 162;
            int o = r / 9, q = r % 9;
            sW[c][r] = w[((long long)o * C + (cc * 32 + cs + c)) * 9 + q];
        }
        __syncthreads();

#pragma unroll
        for (int c = 0; c < 4; c++) {
            float tap[9];
#pragma unroll
            for (int ki = 0; ki < 3; ki++)
#pragma unroll
                for (int kj = 0; kj < 3; kj++) {
                    int xx = x - 1 + kj;
                    float v = 0.f;
                    if (xx >= 0 && xx < WW) v = sIn[c][(lr - 1 + ki) * WW + xx];
                    tap[ki * 3 + kj] = v;
                }
#pragma unroll
            for (int o = 0; o < 18; o++) {
                float s = acc[o];
#pragma unroll
                for (int q = 0; q < 9; q++) s += sW[c][o * 9 + q] * tap[q];
                acc[o] = s;
            }
        }
        __syncthreads();
    }

    float* pp = part + ((long long)cc * 2 + b) * 18 * HW2;
#pragma unroll
    for (int o = 0; o < 18; o++) pp[(long long)o * HW2 + hw] = acc[o];
}

__global__ void reduce18_k(const float* __restrict__ part, float* __restrict__ out, int nc)
{
    int idx = blockIdx.x * 256 + threadIdx.x;
    if (idx >= 2 * 18 * HW2) return;
    int b = idx / (18 * HW2);
    int r = idx % (18 * HW2);
    float s = 0.f;
    for (int c = 0; c < nc; c++) s += part[((long long)c * 2 + b) * 18 * HW2 + r];
    out[(long long)b * 18 * HW2 + r] = s;
}

// ---------------- deformable (or plain) 3x3 s1 p1 im2col (zofs = channel-chunk offset) ----------------
__global__ void deform_im2col_k(const float* __restrict__ src, long long srcB,
                                const float* __restrict__ off,
                                float* __restrict__ colsF,
                                u16* __restrict__ colsH, u16* __restrict__ colsL,
                                int C, int mode, int zofs)
{
    int hw = blockIdx.x * 256 + threadIdx.x;
    if (hw >= HW2) return;
    int bq = blockIdx.y;
    int b = bq / 9, q = bq % 9;
    int ki = q / 3, kj = q % 3;
    int h = hw / WW, w = hw % WW;
    const float* sb = src + (long long)b * srcB;
    long long cbase = (long long)b * C * 9 * HW2;
    int c0 = (blockIdx.z + zofs) * 64;
    int c1 = c0 + 64; if (c1 > C) c1 = C;

    float w00, w01, w10, w11;
    int i00, i01, i10, i11;
    if (off == nullptr) {
        int y = h - 1 + ki, x = w - 1 + kj;
        bool vin = (y >= 0 && y < HH && x >= 0 && x < WW);
        w00 = vin ? 1.f : 0.f; w01 = w10 = w11 = 0.f;
        i00 = vin ? (y * WW + x) : 0; i01 = i10 = i11 = 0;
    } else {
        float py = (float)(h - 1 + ki) + off[((long long)b * 18 + 2 * q) * HW2 + hw];
        float px = (float)(w - 1 + kj) + off[((long long)b * 18 + 2 * q + 1) * HW2 + hw];
        float fy = floorf(py), fx = floorf(px);
        float ay = py - fy, ax = px - fx;
        int y0 = (int)fy, x0 = (int)fx;
        int y1 = y0 + 1, x1 = x0 + 1;
        bool by0 = (y0 >= 0 && y0 < HH), by1 = (y1 >= 0 && y1 < HH);
        bool bx0 = (x0 >= 0 && x0 < WW), bx1 = (x1 >= 0 && x1 < WW);
        int yc0 = min(max(y0, 0), HH - 1), yc1 = min(max(y1, 0), HH - 1);
        int xc0 = min(max(x0, 0), WW - 1), xc1 = min(max(x1, 0), WW - 1);
        w00 = (by0 && bx0) ? (1.f - ay) * (1.f - ax) : 0.f;
        w01 = (by0 && bx1) ? (1.f - ay) * ax : 0.f;
        w10 = (by1 && bx0) ? ay * (1.f - ax) : 0.f;
        w11 = (by1 && bx1) ? ay * ax : 0.f;
        i00 = yc0 * WW + xc0; i01 = yc0 * WW + xc1;
        i10 = yc1 * WW + xc0; i11 = yc1 * WW + xc1;
    }

    for (int c = c0; c < c1; c++) {
        const float* s = sb + (long long)c * HW2;
        float v = w00 * s[i00] + w01 * s[i01] + w10 * s[i10] + w11 * s[i11];
        long long idx = cbase + ((long long)c * 9 + q) * HW2 + hw;
        if (mode == 0) {
            colsF[idx] = v;
        } else {
            u16 hh, ll;
            split16(v, hh, ll);
            colsH[idx] = hh; colsL[idx] = ll;
        }
    }
}

// ---------------- generic strided im2col ----------------
__global__ void im2col_g(const float* __restrict__ src, long long srcB,
                         float* __restrict__ cols,
                         int C, int H, int W, int KH, int KW,
                         int stride, int pad, int OH, int OW)
{
    int ohw = blockIdx.x * 256 + threadIdx.x;
    int OHW = OH * OW;
    if (ohw >= OHW) return;
    int row = blockIdx.y;
    int b = blockIdx.z;
    int kk = row % (KH * KW);
    int c = row / (KH * KW);
    int kh = kk / KW, kw = kk % KW;
    int oh = ohw / OW, ow = ohw % OW;
    int ih = oh * stride - pad + kh;
    int iw = ow * stride - pad + kw;
    float v = 0.f;
    if (ih >= 0 && ih < H && iw >= 0 && iw < W)
        v = src[(long long)b * srcB + ((long long)c * H + ih) * W + iw];
    cols[((long long)b * C * KH * KW + row) * OHW + ohw] = v;
}

// ---------------- direct 3x3 conv (tiny s3: 64->1) ----------------
__global__ void conv3x3_direct(const float* __restrict__ in, long long inB,
                               const float* __restrict__ w, float* __restrict__ out,
                               long long outB, int C, int relu)
{
    int hw = blockIdx.x * 256 + threadIdx.x;
    if (hw >= HW2) return;
    int o = blockIdx.y, b = blockIdx.z;
    int h = hw / WW, x = hw % WW;
    const float* ib = in + (long long)b * inB;
    const float* wo = w + (long long)o * C * 9;
    float acc = 0.f;
    for (int c = 0; c < C; c++) {
        const float* ic = ib + (long long)c * HW2;
        const float* wc = wo + c * 9;
#pragma unroll
        for (int kh = 0; kh < 3; kh++) {
            int ih = h + kh - 1;
            if (ih < 0 || ih >= HH) continue;
#pragma unroll
            for (int kw = 0; kw < 3; kw++) {
                int iw = x + kw - 1;
                if (iw < 0 || iw >= WW) continue;
                acc += ic[ih * WW + iw] * wc[kh * 3 + kw];
            }
        }
    }
    if (relu) acc = fmaxf(acc, 0.f);
    out[(long long)b * outB + (long long)o * HW2 + hw] = acc;
}

// ---------------- elementwise kernels ----------------
__global__ void concat_k(const float* __restrict__ a, const float* __restrict__ b_,
                         float* __restrict__ o, long long imgStride)
{
    int idx = blockIdx.x * 256 + threadIdx.x;
    if (idx >= 2 * 512 * HW2) return;
    int bb = idx / (512 * HW2);
    int c = (idx / HW2) % 512;
    int hw = idx % HW2;
    float v = (c < 256) ? a[bb * imgStride + (long long)c * HW2 + hw]
                        : b_[bb * imgStride + (long long)(c - 256) * HW2 + hw];
    o[idx] = v;
}

__global__ void corr_k(const float* __restrict__ Ra, const float* __restrict__ Tb,
                       float* __restrict__ f177)
{
    int idx = blockIdx.x * 256 + threadIdx.x;
    if (idx >= 2 * 49 * HW2) return;
    int b = idx / (49 * HW2);
    int q = (idx / HW2) % 49;
    int hw = idx % HW2;
    int h = hw / WW, w = hw % WW;
    int dy = 2 * ((q / 7) - 3), dx = 2 * ((q % 7) - 3);
    int hh = h + dy, ww = w + dx;
    float s = 0.f;
    if (hh >= 0 && hh < HH && ww >= 0 && ww < WW) {
        const float* a = Ra + (long long)b * (2 * 64 * HW2) + hw;
        const float* bp = Tb + (long long)b * (2 * 64 * HW2) + hh * WW + ww;
        for (int c = 0; c < 64; c++) s += a[c * HW2] * bp[c * HW2];
    }
    f177[((long long)b * 177 + q) * HW2 + hw] = s * (1.f / 64.f);
}

__global__ void pack_k(const float* __restrict__ eA, const float* __restrict__ eB,
                       float* __restrict__ f177)
{
    int idx = blockIdx.x * 256 + threadIdx.x;
    if (idx >= 2 * 64 * HW2) return;
    int b = idx / (64 * HW2);
    int c = (idx / HW2) % 64;
    int hw = idx % HW2;
    f177[((long long)b * 177 + 49 + c) * HW2 + hw] = eA[idx];
    f177[((long long)b * 177 + 113 + c) * HW2 + hw] = eB[idx];
}

__global__ void mean36_k(const float* __restrict__ in, float* __restrict__ fw, int total)
{
    int i = blockIdx.x * 256 + threadIdx.x;
    if (i >= total) return;
    float s = 0.f;
#pragma unroll
    for (int j = 0; j < 36; j++) s += in[i * 36 + j];
    fw[i] = s * (1.f / 36.f);
}

__global__ void mkw_k(const float* __restrict__ fw, const float* __restrict__ Wt,
                      const float* __restrict__ Bi, float* __restrict__ adw,
                      int M, int Kc, int total)
{
    int idx = blockIdx.x * 256 + threadIdx.x;
    if (idx >= total) return;
    int b = idx / (M * Kc);
    int r = idx - b * M * Kc;
    int o = r / Kc;
    adw[idx] = fw[b * M + o] * Wt[r] + Bi[r];
}

__global__ void final_k(const float* __restrict__ d0, const float* __restrict__ d1,
                        const float* __restrict__ s0p, const float* __restrict__ s1p,
                        float* __restrict__ out, int total)
{
    int idx = blockIdx.x * 256 + threadIdx.x;
    if (idx >= total) return;
    int b = idx / (256 * HW2);
    int hw = idx % HW2;
    float s0 = s0p[b * HW2 + hw];
    float s1 = s1p[b * HW2 + hw];
    const float eps = 1e-8f;
    float wx = (s0 * s1) / (fmaxf(fabsf(s0), eps) * fmaxf(fabsf(s1), eps));
    float wy = (s1 * s1) / (fmaxf(fabsf(s1), eps) * fmaxf(fabsf(s1), eps));
    float mx = fmaxf(wx, wy);
    float e0 = expf(wx - mx), e1 = expf(wy - mx);
    float inv = 1.f / (e0 + e1);
    out[idx] = d0[idx] * (e0 * inv) + d1[idx] * (e1 * inv);
}

// ---------------- host orchestration (capture-legal critical-path trim) ----------------
extern "C" void kernel_launch(void* const* d_in, const int* in_sizes, int n_in,
                              void* d_out, int out_size)
{
    (void)in_sizes; (void)n_in; (void)out_size;
    const float* R0     = (const float*)d_in[0];
    const float* T0     = (const float*)d_in[1];
    const float* inp    = (const float*)d_in[2];
    const float* enc0_w = (const float*)d_in[3];
    const float* enc0_b = (const float*)d_in[4];
    const float* enc1_w = (const float*)d_in[5];
    const float* enc1_b = (const float*)d_in[6];
    const float* offw[4] = {(const float*)d_in[7], (const float*)d_in[8],
                            (const float*)d_in[9], (const float*)d_in[10]};
    const float* defw[3] = {(const float*)d_in[11], (const float*)d_in[12],
                            (const float*)d_in[13]};
    const float* w0a = (const float*)d_in[14];
    const float* w0b = (const float*)d_in[15];
    const float* w0c = (const float*)d_in[16];
    const float* w1a = (const float*)d_in[17];
    const float* w1b = (const float*)d_in[18];
    const float* w1c = (const float*)d_in[19];
    const float* wx_w  = (const float*)d_in[20];
    const float* wx_b  = (const float*)d_in[21];
    const float* wxf_w = (const float*)d_in[22];
    const float* wxf_b = (const float*)d_in[23];
    const float* s1w = (const float*)d_in[24];
    const float* s2w = (const float*)d_in[25];
    const float* s3w = (const float*)d_in[26];
    float* out = (float*)d_out;

    float *xenc, *yenc, *def0, *def1, *swa, *swb;
    float *f512aP, *f512bP, *colsP, *offP, *cpartP, *f177P, *f177bP;
    float *wb1P, *wb2P, *wb3P, *fwP, *adwP, *s1oP, *s2oP, *o0f;
    u16 *colshP, *colslP, *awhP, *awlP, *dwh, *dwl, *s1h, *s1l, *d0fh, *d0fl;
    cudaGetSymbolAddress((void**)&xenc,   g_xenc);
    cudaGetSymbolAddress((void**)&yenc,   g_yenc);
    cudaGetSymbolAddress((void**)&f512aP, g_f512a);
    cudaGetSymbolAddress((void**)&f512bP, g_f512b);
    cudaGetSymbolAddress((void**)&colsP,  g_cols);
    cudaGetSymbolAddress((void**)&colshP, g_colsh);
    cudaGetSymbolAddress((void**)&colslP, g_colsl);
    cudaGetSymbolAddress((void**)&awhP,   g_awh);
    cudaGetSymbolAddress((void**)&awlP,   g_awl);
    cudaGetSymbolAddress((void**)&dwh,    g_dwh);
    cudaGetSymbolAddress((void**)&dwl,    g_dwl);
    cudaGetSymbolAddress((void**)&d0fh,   g_d0fh);
    cudaGetSymbolAddress((void**)&d0fl,   g_d0fl);
    cudaGetSymbolAddress((void**)&o0f,    g_o0f);
    cudaGetSymbolAddress((void**)&s1h,    g_s1h);
    cudaGetSymbolAddress((void**)&s1l,    g_s1l);
    cudaGetSymbolAddress((void**)&offP,   g_offb);
    cudaGetSymbolAddress((void**)&cpartP, g_cpart);
    cudaGetSymbolAddress((void**)&f177P,  g_f177);
    cudaGetSymbolAddress((void**)&f177bP, g_f177b);
    cudaGetSymbolAddress((void**)&wb1P,   g_wb1);
    cudaGetSymbolAddress((void**)&wb2P,   g_wb2);
    cudaGetSymbolAddress((void**)&wb3P,   g_wb3);
    cudaGetSymbolAddress((void**)&fwP,    g_fwb);
    cudaGetSymbolAddress((void**)&adwP,   g_adw);
    cudaGetSymbolAddress((void**)&def0,   g_def0);
    cudaGetSymbolAddress((void**)&def1,   g_def1);
    cudaGetSymbolAddress((void**)&s1oP,   g_s1o);
    cudaGetSymbolAddress((void**)&s2oP,   g_s2o);
    cudaGetSymbolAddress((void**)&swa,    g_swa);
    cudaGetSymbolAddress((void**)&swb,    g_swb);

    auto F512A = [&](int br){ return f512aP + (long long)br * (2*512*HW2); };
    auto F512B = [&](int br){ return f512bP + (long long)br * (2*512*HW2); };
    auto COLS  = [&](int br){ return colsP  + (long long)br * (2*1600*HW2); };
    auto COLSH = [&](int br){ return colshP + (long long)br * (2LL*4608*HW2); };
    auto COLSL = [&](int br){ return colslP + (long long)br * (2LL*4608*HW2); };
    auto AWH   = [&](int br){ return awhP   + (long long)br * (2*256*2304); };
    auto AWL   = [&](int br){ return awlP   + (long long)br * (2*256*2304); };
    auto OFF   = [&](int br){ return offP   + (long long)br * (2*18*HW2); };
    auto CPART = [&](int br){ return cpartP + (long long)br * (16LL*2*18*HW2); };
    auto F177  = [&](int br){ return f177P  + (long long)br * (2*177*HW2); };
    auto F177B = [&](int br){ return f177bP + (long long)br * (2*177*HW2); };
    auto WB1   = [&](int br){ return wb1P + (long long)br * (2*64*576); };
    auto WB2   = [&](int br){ return wb2P + (long long)br * (2*64*144); };
    auto WB3   = [&](int br){ return wb3P + (long long)br * (2*256*36); };
    auto FW    = [&](int br){ return fwP  + (long long)br * (2*256); };
    auto ADW   = [&](int br){ return adwP + (long long)br * (2*256*HW2); };
    auto S1O   = [&](int br){ return s1oP + (long long)br * (2*128*HW2); };
    auto S2O   = [&](int br){ return s2oP + (long long)br * (2*64*HW2); };

    const long long imgStride = 2LL * 256 * HW2;
    const int DW = 512 * 4608;

    cudaStream_t sM = 0, sW0, sS1, sW1;
    cudaStreamCreateWithFlags(&sW0, cudaStreamNonBlocking);
    cudaStreamCreateWithFlags(&sS1, cudaStreamNonBlocking);
    cudaStreamCreateWithFlags(&sW1, cudaStreamNonBlocking);
    const int NEV = 8;
    cudaEvent_t ev[NEV];
    for (int i = 0; i < NEV; i++) cudaEventCreateWithFlags(&ev[i], cudaEventDisableTiming);
    int evi = 0;
    auto FORK = [&](cudaStream_t from, cudaStream_t to) {
        cudaEventRecord(ev[evi], from);
        cudaStreamWaitEvent(to, ev[evi], 0);
        evi++;
    };

    auto GEMMTB = [&](cudaStream_t st, const u16* Ah, const u16* Al,
                      const u16* Bh, const u16* Bl, float* C,
                      int M, int N, int K,
                      long long sA, long long sB, long long sC, int relu) {
        gemm_bf3b<<<dim3(N / 64, M / 128, 2), 256, 0, st>>>(Ah, Al, Bh, Bl,
                                                            C, M, N, K, sA, sB, sC, relu);
    };
    auto GEMMA = [&](cudaStream_t st, const float* A, const float* Bm, float* C,
                     int M, int N, int K, long long sA, long long sB, long long sC,
                     const float* bias, int relu) {
        gemm_al<4><<<dim3(N / 64, M / 64, 2), 256, 0, st>>>(A, Bm, C, M, N, K,
                                                            sA, sB, sC, bias, relu);
    };
    auto GEMMF = [&](cudaStream_t st, const float* A, const float* Bm, float* C,
                     int M, int N, int K, long long sA, long long sB, long long sC,
                     const float* bias, int relu) {
        dim3 g((N + 63) / 64, (M + 63) / 64, 2);
        gemm64<<<g, dim3(16, 16), 0, st>>>(A, Bm, C, M, N, K, sA, sB, sC, bias, relu);
    };
    auto DIM2COL = [&](cudaStream_t st, const float* src, long long sB,
                       const float* offp, int C, int mode, int br, int zofs, int zcnt) {
        dim3 g((HW2 + 255) / 256, 18, zcnt);
        deform_im2col_k<<<g, 256, 0, st>>>(src, sB, offp, COLS(br),
                                           COLSH(br), COLSL(br), C, mode, zofs);
    };
    auto IM2COL = [&](cudaStream_t st, const float* src, long long sB, int C,
                      int H, int W, int KH, int KW, int stp, int pad,
                      int OH, int OW, int br) {
        dim3 g((OH * OW + 255) / 256, C * KH * KW, 2);
        im2col_g<<<g, 256, 0, st>>>(src, sB, COLS(br), C, H, W, KH, KW, stp, pad, OH, OW);
    };
    auto WBRANCH = [&](cudaStream_t st, const float* feat, const float* wa,
                       const float* wb, const float* wc, int Mc, int br) {
        IM2COL(st, feat, 177LL * HW2, 177, 48, 48, 5, 5, 2, 2, 24, 24, br);
        GEMMF(st, wa, COLS(br), WB1(br), 64, 576, 4425, 0, 4425LL * 576, 64LL * 576,
              nullptr, 1);
        IM2COL(st, WB1(br), 64LL * 576, 64, 24, 24, 5, 5, 2, 2, 12, 12, br);
        GEMMF(st, wb, COLS(br), WB2(br), 64, 144, 1600, 0, 1600LL * 144, 64LL * 144,
              nullptr, 1);
        IM2COL(st, WB2(br), 64LL * 144, 64, 12, 12, 3, 3, 2, 1, 6, 6, br);
        GEMMF(st, wc, COLS(br), WB3(br), Mc, 36, 576, 0, 576LL * 36,
              (long long)Mc * 36, nullptr, 0);
        int tot = 2 * Mc;
        mean36_k<<<(tot + 255) / 256, 256, 0, st>>>(WB3(br), FW(br), tot);
    };

    // ---- capture-legal fork: ev0 on sM first, all side streams join on it ----
    {
        cudaEventRecord(ev[evi], sM);
        cudaStreamWaitEvent(sW0, ev[evi], 0);
        evi++;
    }

    // ---- init on sM: ONLY what STSN needs (weight splits + folds) ----
    for (int i = 0; i < 3; i++)
        convw_k<<<(DW + 255) / 256, 256, 0, sM>>>(defw[i], dwh + (long long)i * DW,
                                                  dwl + (long long)i * DW, DW);
    convw_k<<<(128 * 2304 + 255) / 256, 256, 0, sM>>>(s1w, s1h, s1l, 128 * 2304);
    foldw_k<<<(512 * 2304 + 255) / 256, 256, 0, sM>>>(defw[0], d0fh, d0fl, 512, 256);
    foldf_k<<<(18 * 256 * 9 + 255) / 256, 256, 0, sM>>>(offw[0], o0f, 18, 256);
    FORK(sM, sS1);   // sS1 (branch-1 STSN) needs o0f/d0fh/dwh

    // ---- encoders off the critical path: on sW0 (joined capture above) ----
    GEMMA(sW0, enc0_w, inp,             xenc, 64, HW2, 256, 0, imgStride, 64LL * HW2, enc0_b, 0);
    GEMMA(sW0, enc1_w, inp + 256 * HW2, yenc, 64, HW2, 256, 0, imgStride, 64LL * HW2, enc1_b, 0);
    FORK(sW0, sW1);  // WEIGHT1 needs yenc

    // STSN; branch 1 iter-0 uses the (y,y) fold: C=256, K=2304, no concat
    auto STSN = [&](cudaStream_t st, int br) {
        const float* imgA = (br == 0) ? inp : inp + 256 * HW2;
        const float* imgB = inp + 256 * HW2;
        float* cur; float* oth;
        if (br == 0) {
            int tot = 2 * 512 * HW2;
            concat_k<<<(tot + 255) / 256, 256, 0, st>>>(imgA, imgB, F512A(br), imgStride);
            cur = F512A(br); oth = F512B(br);
            conv18_k<<<dim3(9, 16, 2), 256, 0, st>>>(cur, 512LL * HW2, offw[0],
                                                     CPART(br), 512);
            reduce18_k<<<(2 * 18 * HW2 + 255) / 256, 256, 0, st>>>(CPART(br), OFF(br), 16);
            DIM2COL(st, cur, 512LL * HW2, OFF(br), 512, 1, br, 0, 8);
            GEMMTB(st, dwh, dwl, COLSH(br), COLSL(br), oth, 512, HW2, 4608,
                   0, 4608LL * HW2, 512LL * HW2, 0);
        } else {
            // folded iter 0 directly on y
            conv18_k<<<dim3(9, 8, 2), 256, 0, st>>>(imgB, imgStride, o0f,
                                                    CPART(br), 256);
            reduce18_k<<<(2 * 18 * HW2 + 255) / 256, 256, 0, st>>>(CPART(br), OFF(br), 8);
            DIM2COL(st, imgB, imgStride, OFF(br), 256, 1, br, 0, 4);
            GEMMTB(st, d0fh, d0fl, COLSH(br), COLSL(br), F512B(br), 512, HW2, 2304,
                   0, 2304LL * HW2, 512LL * HW2, 0);
            oth = F512B(br);
        }
        cur = oth; oth = (cur == F512A(br)) ? F512B(br) : F512A(br);
        for (int i = 1; i < 3; i++) {
            conv18_k<<<dim3(9, 16, 2), 256, 0, st>>>(cur, 512LL * HW2, offw[i],
                                                     CPART(br), 512);
            reduce18_k<<<(2 * 18 * HW2 + 255) / 256, 256, 0, st>>>(CPART(br), OFF(br), 16);
            DIM2COL(st, cur, 512LL * HW2, OFF(br), 512, 1, br, 0, 8);
            GEMMTB(st, dwh + (long long)i * DW, dwl + (long long)i * DW,
                   COLSH(br), COLSL(br), oth, 512, HW2, 4608,
                   0, 4608LL * HW2, 512LL * HW2, 0);
            float* t = cur; cur = oth; oth = t;
        }
        conv18_k<<<dim3(9, 16, 2), 256, 0, st>>>(cur, 512LL * HW2, offw[3],
                                                 CPART(br), 512);
        reduce18_k<<<(2 * 18 * HW2 + 255) / 256, 256, 0, st>>>(CPART(br), OFF(br), 16);
    };

    auto WEIGHT = [&](cudaStream_t st, int br) {
        const float* Ra = R0 + (br == 0 ? 0 : 64 * HW2);
        const float* Tb = T0 + 64 * HW2;
        const float* eA = (br == 0) ? xenc : yenc;
        const float* eB = yenc;
        int tot = 2 * 49 * HW2;
        corr_k<<<(tot + 255) / 256, 256, 0, st>>>(Ra, Tb, F177(br));
        tot = 2 * 64 * HW2;
        pack_k<<<(tot + 255) / 256, 256, 0, st>>>(eA, eB, F177(br));
        WBRANCH(st, F177(br), w0a, w0b, w0c, 177, br);
        tot = 2 * 177 * 1593;
        mkw_k<<<(tot + 255) / 256, 256, 0, st>>>(FW(br), wx_w, wx_b, ADW(br), 177, 1593, tot);
        DIM2COL(st, F177(br), 177LL * HW2, nullptr, 177, 0, br, 0, 3);
        GEMMF(st, ADW(br), COLS(br), F177B(br), 177, HW2, 1593,
              177LL * 1593, 1593LL * HW2, 177LL * HW2, nullptr, 1);
        WBRANCH(st, F177B(br), w1a, w1b, w1c, 256, br);
        tot = 2 * 256 * 2304;
        mkw_k<<<(tot + 255) / 256, 256, 0, st>>>(FW(br), wxf_w, wxf_b, ADW(br), 256, 2304, tot);
        convw_k<<<(2 * 256 * 2304 + 255) / 256, 256, 0, st>>>(ADW(br), AWH(br), AWL(br),
                                                              2 * 256 * 2304);
    };

    // TAIL: adaptive dim2col issued BEFORE the WEIGHT join (needs only OFF + img)
    auto TAILPRE = [&](cudaStream_t st, int br) {
        const float* imgA = (br == 0) ? inp : inp + 256 * HW2;
        DIM2COL(st, imgA, imgStride, OFF(br), 256, 1, br, 0, 4);
    };
    auto TAIL = [&](cudaStream_t st, int br, float* gdef, float* gsw) {
        GEMMTB(st, AWH(br), AWL(br), COLSH(br), COLSL(br), gdef, 256, HW2, 2304,
               256LL * 2304, 2304LL * HW2, 256LL * HW2, 0);
        DIM2COL(st, gdef, 256LL * HW2, nullptr, 256, 1, br, 0, 4);
        GEMMTB(st, s1h, s1l, COLSH(br), COLSL(br), S1O(br), 128, HW2, 2304,
               0, 2304LL * HW2, 128LL * HW2, 1);
        DIM2COL(st, S1O(br), 128LL * HW2, nullptr, 128, 0, br, 0, 2);
        GEMMA(st, s2w, COLS(br), S2O(br), 64, HW2, 1152,
              0, 1152LL * HW2, 64LL * HW2, nullptr, 1);
        conv3x3_direct<<<dim3(9, 1, 2), 256, 0, st>>>(S2O(br), 64LL * HW2, s3w, gsw,
                                                      (long long)HW2, 64, 1);
    };

    // branch 0: stsn on sM, weight on sW0
    STSN(sM, 0);
    WEIGHT(sW0, 0);
    TAILPRE(sM, 0);
    FORK(sW0, sM);
    TAIL(sM, 0, def0, swa);

    // branch 1: stsn on sS1, weight on sW1
    STSN(sS1, 1);
    WEIGHT(sW1, 1);
    TAILPRE(sS1, 1);
    FORK(sW1, sS1);
    TAIL(sS1, 1, def1, swb);
    FORK(sS1, sM);

    {
        int tot = 2 * 256 * HW2;
        final_k<<<(tot + 255) / 256, 256, 0, sM>>>(def0, def1, swa, swb, out, tot);
    }

    for (int i = 0; i < NEV; i++) cudaEventDestroy(ev[i]);
    cudaStreamDestroy(sW0);
    cudaStreamDestroy(sS1);
    cudaStreamDestroy(sW1);
}